// round 1
// baseline (speedup 1.0000x reference)
#include <cuda_runtime.h>

typedef unsigned long long ull;

#define CB 64      // batch
#define CT 128     // time
#define CE 256     // embed
#define CH 1024    // hidden
#define CG 4096    // 4*H
#define NCTA 128   // persistent recurrence grid

// -------- scratch (device globals; no runtime allocation) --------
__device__ float g_xz[(size_t)CT * CB * CG];   // shared by layer1 & layer2 (134 MB)
__device__ float g_y1[(size_t)CT * CB * CH];   // layer1 outputs, time-major [t][b][h]
__device__ float g_hT[2][CH * CB];             // transposed h, double buffered [k][b]
__device__ float g_cT[CH * CB];                // transposed c [k][b]
__device__ unsigned g_bar;                     // monotonic grid-barrier counter

// -------- packed fp32 helpers (sm_100+ f32x2 path) --------
__device__ __forceinline__ ull ffma2(ull a, ull b, ull c) {
    ull d; asm("fma.rn.f32x2 %0,%1,%2,%3;" : "=l"(d) : "l"(a), "l"(b), "l"(c)); return d;
}
__device__ __forceinline__ ull pack2(float x, float y) {
    ull d; asm("mov.b64 %0,{%1,%2};" : "=l"(d) : "f"(x), "f"(y)); return d;
}
__device__ __forceinline__ float2 unpack2(ull v) {
    float2 r; asm("mov.b64 {%0,%1},%2;" : "=f"(r.x), "=f"(r.y) : "l"(v)); return r;
}

__device__ __forceinline__ float sigmoidf_(float x) { return 1.f / (1.f + __expf(-x)); }

// Monotonic-counter grid barrier (no reset race; safe across graph replays).
__device__ __forceinline__ void grid_sync() {
    __threadfence();
    __syncthreads();
    if (threadIdx.x == 0) {
        unsigned old = atomicAdd(&g_bar, 1u);
        unsigned target = (old / NCTA + 1u) * NCTA;
        while (*((volatile unsigned*)&g_bar) < target) {}
        __threadfence();
    }
    __syncthreads();
}

// ============================================================================
// GEMM: C[M=8192, N=4096] = A[M,K] @ W[K,N] + bias, optional row gather (emb).
// BM=BN=128, BK=16, 256 threads, 8x8 micro-tile, f32x2 packed FMA,
// smem double buffer with register prefetch.
// ============================================================================
template <bool GATHER>
__global__ __launch_bounds__(256) void gemm_bias_kernel(
    const float* __restrict__ A, const int* __restrict__ xidx,
    const float* __restrict__ W, const float* __restrict__ bias,
    float* __restrict__ C, int K)
{
    __shared__ float As[2][16][132];   // transposed A tile [k][m], padded
    __shared__ float Ws[2][16][128];   // W tile [k][n]

    const int tid  = threadIdx.x;
    const int n0   = blockIdx.x * 128;
    const int m0   = blockIdx.y * 128;
    const int trow = tid >> 4;         // 0..15
    const int tcol = tid & 15;         // 0..15

    // ---- A staging map: 2 rows / thread ----
    const int sr  = tid >> 2;          // 0..63
    const int skq = (tid & 3) * 4;     // 0,4,8,12
    const float* arow0;
    const float* arow1;
    {
        int ma = m0 + sr, mb = m0 + sr + 64;
        if (GATHER) {
            int ia = xidx[(ma % CB) * CT + (ma / CB)];
            int ib = xidx[(mb % CB) * CT + (mb / CB)];
            arow0 = A + (size_t)ia * K;
            arow1 = A + (size_t)ib * K;
        } else {
            arow0 = A + (size_t)ma * K;
            arow1 = A + (size_t)mb * K;
        }
    }
    // ---- W staging map: 2 float4 / thread ----
    const int wk  = tid >> 5;          // 0..7
    const int wc4 = (tid & 31) * 4;    // 0..124

    ull acc[8][4];
#pragma unroll
    for (int r = 0; r < 8; ++r)
#pragma unroll
        for (int j = 0; j < 4; ++j) acc[r][j] = pack2(0.f, 0.f);

    const int nk = K / 16;
    float4 pa0, pa1, pw0, pw1;

    pa0 = *(const float4*)(arow0 + skq);
    pa1 = *(const float4*)(arow1 + skq);
    pw0 = *(const float4*)(W + (size_t)wk * CG + n0 + wc4);
    pw1 = *(const float4*)(W + (size_t)(wk + 8) * CG + n0 + wc4);

    As[0][skq + 0][sr] = pa0.x; As[0][skq + 1][sr] = pa0.y;
    As[0][skq + 2][sr] = pa0.z; As[0][skq + 3][sr] = pa0.w;
    As[0][skq + 0][sr + 64] = pa1.x; As[0][skq + 1][sr + 64] = pa1.y;
    As[0][skq + 2][sr + 64] = pa1.z; As[0][skq + 3][sr + 64] = pa1.w;
    *(float4*)&Ws[0][wk][wc4]     = pw0;
    *(float4*)&Ws[0][wk + 8][wc4] = pw1;
    __syncthreads();

    int p = 0;
    for (int kt = 0; kt < nk; ++kt) {
        const int k0n = (kt + 1) * 16;
        if (kt + 1 < nk) {
            pa0 = *(const float4*)(arow0 + k0n + skq);
            pa1 = *(const float4*)(arow1 + k0n + skq);
            pw0 = *(const float4*)(W + (size_t)(k0n + wk) * CG + n0 + wc4);
            pw1 = *(const float4*)(W + (size_t)(k0n + wk + 8) * CG + n0 + wc4);
        }
#pragma unroll
        for (int kk = 0; kk < 16; ++kk) {
            float4 a0 = *(const float4*)&As[p][kk][trow * 8];
            float4 a1 = *(const float4*)&As[p][kk][trow * 8 + 4];
            ulonglong2 b01 = *(const ulonglong2*)&Ws[p][kk][tcol * 8];
            ulonglong2 b23 = *(const ulonglong2*)&Ws[p][kk][tcol * 8 + 4];
            float av[8] = {a0.x, a0.y, a0.z, a0.w, a1.x, a1.y, a1.z, a1.w};
            ull bv[4] = {b01.x, b01.y, b23.x, b23.y};
#pragma unroll
            for (int r = 0; r < 8; ++r) {
                ull ad = pack2(av[r], av[r]);
#pragma unroll
                for (int j = 0; j < 4; ++j) acc[r][j] = ffma2(ad, bv[j], acc[r][j]);
            }
        }
        if (kt + 1 < nk) {
            int q = p ^ 1;
            As[q][skq + 0][sr] = pa0.x; As[q][skq + 1][sr] = pa0.y;
            As[q][skq + 2][sr] = pa0.z; As[q][skq + 3][sr] = pa0.w;
            As[q][skq + 0][sr + 64] = pa1.x; As[q][skq + 1][sr + 64] = pa1.y;
            As[q][skq + 2][sr + 64] = pa1.z; As[q][skq + 3][sr + 64] = pa1.w;
            *(float4*)&Ws[q][wk][wc4]     = pw0;
            *(float4*)&Ws[q][wk + 8][wc4] = pw1;
        }
        __syncthreads();
        p ^= 1;
    }

    // epilogue: add bias, store
    float bv[8];
#pragma unroll
    for (int j = 0; j < 8; ++j) bv[j] = bias[n0 + tcol * 8 + j];
#pragma unroll
    for (int r = 0; r < 8; ++r) {
        float* crow = C + (size_t)(m0 + trow * 8 + r) * CG + n0 + tcol * 8;
        float2 t0 = unpack2(acc[r][0]), t1 = unpack2(acc[r][1]);
        float2 t2 = unpack2(acc[r][2]), t3 = unpack2(acc[r][3]);
        float4 v0 = {t0.x + bv[0], t0.y + bv[1], t1.x + bv[2], t1.y + bv[3]};
        float4 v1 = {t2.x + bv[4], t2.y + bv[5], t3.x + bv[6], t3.y + bv[7]};
        *(float4*)(crow)     = v0;
        *(float4*)(crow + 4) = v1;
    }
}

// ============================================================================
// Persistent LSTM layer. 128 CTAs x 256 threads. CTA j owns hidden cols
// [8j, 8j+8) across all 4 gates and all 64 batch rows. One grid barrier/step.
// h kept transposed [k][b] (double buffered) so staging and updates coalesce.
// ============================================================================
__global__ __launch_bounds__(256) void lstm_kernel(
    const float* __restrict__ xz, const float* __restrict__ U,
    float* __restrict__ y, int y_ts, int y_bs,
    const float* __restrict__ h0, const float* __restrict__ c0,
    float* __restrict__ hOut, float* __restrict__ cOut)
{
    __shared__ float sH[2][32][64];    // h chunk, transposed [k][b]
    __shared__ float sU[2][32][32];    // U chunk [k][col]
    __shared__ float sZ[64][33];       // z tile [b][col], padded

    const int tid = threadIdx.x;
    const int cta = blockIdx.x;
    const int hj  = cta * 8;

    // init transposed h, c from initial states (all CTAs cooperate)
    for (int e = cta * 256 + tid; e < CB * CH; e += NCTA * 256) {
        int b = e >> 10, k = e & (CH - 1);
        g_hT[0][k * CB + b] = h0[e];
        g_cT[k * CB + b]    = c0[e];
    }

    // compute-thread mapping: col c (gate*8 + hid), 8 batch rows starting r0
    const int c    = tid & 31;
    const int r0   = (tid >> 5) * 8;
    const int gate = c >> 3;
    const int gc   = gate * CH + hj + (c & 7);

    // staging maps
    const int hk0 = tid >> 4;                 // 0..15  (k within chunk)
    const int hb0 = (tid & 15) * 4;           // 0..60  (b, float4)
    const int uk  = tid >> 3;                 // 0..31
    const int useg = tid & 7;
    const int ucol = (useg >> 1) * CH + hj + (useg & 1) * 4;
    const int usmc = useg * 4;

    for (int t = 0; t < CT; ++t) {
        grid_sync();   // h[t] buffer fully written by all CTAs

        const float* hR  = g_hT[t & 1];
        const float* xzp = xz + ((size_t)t * CB) * CG + gc;

        // init accumulators with the precomputed input projection
        ull a0 = pack2(xzp[(r0 + 0) * CG], xzp[(r0 + 1) * CG]);
        ull a1 = pack2(xzp[(r0 + 2) * CG], xzp[(r0 + 3) * CG]);
        ull a2 = pack2(xzp[(r0 + 4) * CG], xzp[(r0 + 5) * CG]);
        ull a3 = pack2(xzp[(r0 + 6) * CG], xzp[(r0 + 7) * CG]);

        float4 ph0 = *(const float4*)(hR + hk0 * CB + hb0);
        float4 ph1 = *(const float4*)(hR + (hk0 + 16) * CB + hb0);
        float4 pu  = *(const float4*)(U + (size_t)uk * CG + ucol);
        *(float4*)&sH[0][hk0][hb0]      = ph0;
        *(float4*)&sH[0][hk0 + 16][hb0] = ph1;
        *(float4*)&sU[0][uk][usmc]      = pu;
        __syncthreads();

        int p = 0;
        for (int kc = 0; kc < CH / 32; ++kc) {
            const int k0n = (kc + 1) * 32;
            if (kc + 1 < CH / 32) {
                ph0 = *(const float4*)(hR + (k0n + hk0) * CB + hb0);
                ph1 = *(const float4*)(hR + (k0n + hk0 + 16) * CB + hb0);
                pu  = *(const float4*)(U + (size_t)(k0n + uk) * CG + ucol);
            }
#pragma unroll 8
            for (int kk = 0; kk < 32; ++kk) {
                ulonglong2 h01 = *(const ulonglong2*)&sH[p][kk][r0];
                ulonglong2 h23 = *(const ulonglong2*)&sH[p][kk][r0 + 4];
                float uv = sU[p][kk][c];
                ull  u2  = pack2(uv, uv);
                a0 = ffma2(h01.x, u2, a0);
                a1 = ffma2(h01.y, u2, a1);
                a2 = ffma2(h23.x, u2, a2);
                a3 = ffma2(h23.y, u2, a3);
            }
            if (kc + 1 < CH / 32) {
                int q = p ^ 1;
                *(float4*)&sH[q][hk0][hb0]      = ph0;
                *(float4*)&sH[q][hk0 + 16][hb0] = ph1;
                *(float4*)&sU[q][uk][usmc]      = pu;
            }
            __syncthreads();
            p ^= 1;
        }

        // z tile -> smem for gate fusion
        {
            float2 v;
            v = unpack2(a0); sZ[r0 + 0][c] = v.x; sZ[r0 + 1][c] = v.y;
            v = unpack2(a1); sZ[r0 + 2][c] = v.x; sZ[r0 + 3][c] = v.y;
            v = unpack2(a2); sZ[r0 + 4][c] = v.x; sZ[r0 + 5][c] = v.y;
            v = unpack2(a3); sZ[r0 + 6][c] = v.x; sZ[r0 + 7][c] = v.y;
        }
        __syncthreads();

        float* hW = g_hT[(t + 1) & 1];
#pragma unroll
        for (int i = 0; i < 2; ++i) {
            int idx = tid + i * 256;     // 0..511
            int hid = idx >> 6;          // 0..7
            int b   = idx & 63;
            float zi = sZ[b][hid];
            float zf = sZ[b][8 + hid];
            float zg = sZ[b][16 + hid];
            float zo = sZ[b][24 + hid];
            int koff = (hj + hid) * CB + b;
            float cp = g_cT[koff];
            float fi = sigmoidf_(zi);
            float ff = sigmoidf_(zf);
            float gg = tanhf(zg);
            float fo = sigmoidf_(zo);
            float cn = ff * cp + fi * gg;
            float hn = fo * tanhf(cn);
            g_cT[koff] = cn;
            hW[koff]   = hn;
            y[(size_t)t * y_ts + (size_t)b * y_bs + hj + hid] = hn;
            if (t == CT - 1) {
                hOut[b * CH + hj + hid] = hn;
                cOut[b * CH + hj + hid] = cn;
            }
        }
        // next iteration's grid_sync (with its __syncthreads) protects sZ/sH reuse
    }
}

// ============================================================================
extern "C" void kernel_launch(void* const* d_in, const int* in_sizes, int n_in,
                              void* d_out, int out_size)
{
    const int*   x   = (const int*)  d_in[0];
    const float* h01 = (const float*)d_in[1];
    const float* c01 = (const float*)d_in[2];
    const float* h02 = (const float*)d_in[3];
    const float* c02 = (const float*)d_in[4];
    const float* emb = (const float*)d_in[5];
    const float* W1  = (const float*)d_in[6];
    const float* U1  = (const float*)d_in[7];
    const float* b1  = (const float*)d_in[8];
    const float* W2  = (const float*)d_in[9];
    const float* U2  = (const float*)d_in[10];
    const float* b2  = (const float*)d_in[11];

    float* out = (float*)d_out;
    float* h1o = out + (size_t)CB * CT * CH;
    float* c1o = h1o + CB * CH;
    float* h2o = c1o + CB * CH;
    float* c2o = h2o + CB * CH;

    float *xz, *y1;
    cudaGetSymbolAddress((void**)&xz, g_xz);
    cudaGetSymbolAddress((void**)&y1, g_y1);

    dim3 gg(CG / 128, (CT * CB) / 128);   // (32, 64)

    // layer 1: embedding-gathered input projection, then recurrence
    gemm_bias_kernel<true><<<gg, 256>>>(emb, x, W1, b1, xz, CE);
    lstm_kernel<<<NCTA, 256>>>(xz, U1, y1, CB * CH, CH, h01, c01, h1o, c1o);

    // layer 2: input projection from y1 (reuses xz buffer), then recurrence
    gemm_bias_kernel<false><<<gg, 256>>>(y1, nullptr, W2, b2, xz, CH);
    lstm_kernel<<<NCTA, 256>>>(xz, U2, out, CH, CT * CH, h02, c02, h2o, c2o);
}

// round 6
// speedup vs baseline: 1.5304x; 1.5304x over previous
#include <cuda_runtime.h>
#include <cstdint>

typedef unsigned long long ull;

#define CB 64      // batch
#define CT 128     // time
#define CE 256     // embed
#define CH 1024    // hidden
#define CG 4096    // 4*H
#define NCTA 128   // persistent recurrence grid
#define NTHR 256

// -------- scratch (device globals; no runtime allocation) --------
__device__ float g_xz[(size_t)CT * CB * CG];   // shared by layer1 & layer2
__device__ float g_y1[(size_t)CT * CB * CH];   // layer1 outputs [t][b][h]
__device__ float g_h[2][CB * CH];              // h state, b-major [b][k], double buffered
__device__ float g_c[CB * CH];                 // c state, b-major [b][k]
__device__ unsigned g_bar;                     // monotonic grid-barrier counter

// -------- packed fp32 helpers --------
__device__ __forceinline__ ull ffma2(ull a, ull b, ull c) {
    ull d; asm("fma.rn.f32x2 %0,%1,%2,%3;" : "=l"(d) : "l"(a), "l"(b), "l"(c)); return d;
}
__device__ __forceinline__ ull pack2(float x, float y) {
    ull d; asm("mov.b64 %0,{%1,%2};" : "=l"(d) : "f"(x), "f"(y)); return d;
}
__device__ __forceinline__ float2 unpack2(ull v) {
    float2 r; asm("mov.b64 {%0,%1},%2;" : "=f"(r.x), "=f"(r.y) : "l"(v)); return r;
}

__device__ __forceinline__ float sigm_(float x)  { return __fdividef(1.f, 1.f + __expf(-x)); }
__device__ __forceinline__ float tanhf_(float x) { return __fdividef(2.f, 1.f + __expf(-2.f * x)) - 1.f; }

// Monotonic-counter grid barrier (no reset race; safe across graph replays).
__device__ __forceinline__ void grid_sync() {
    __threadfence();
    __syncthreads();
    if (threadIdx.x == 0) {
        unsigned old = atomicAdd(&g_bar, 1u);
        unsigned target = (old / NCTA + 1u) * NCTA;
        while (*((volatile unsigned*)&g_bar) < target) {}
        __threadfence();
    }
    __syncthreads();
}

// ============================================================================
// GEMM: C[M, 4096] = A[M,K] @ W[K,4096] + bias, optional row gather (emb).
// ============================================================================
template <bool GATHER>
__global__ __launch_bounds__(256) void gemm_bias_kernel(
    const float* __restrict__ A, const int* __restrict__ xidx,
    const float* __restrict__ W, const float* __restrict__ bias,
    float* __restrict__ C, int K)
{
    __shared__ float As[2][16][132];
    __shared__ float Ws[2][16][128];

    const int tid  = threadIdx.x;
    const int n0   = blockIdx.x * 128;
    const int m0   = blockIdx.y * 128;
    const int trow = tid >> 4;
    const int tcol = tid & 15;

    const int sr  = tid >> 2;
    const int skq = (tid & 3) * 4;
    const float* arow0;
    const float* arow1;
    {
        int ma = m0 + sr, mb = m0 + sr + 64;
        if (GATHER) {
            int ia = xidx[(ma % CB) * CT + (ma / CB)];
            int ib = xidx[(mb % CB) * CT + (mb / CB)];
            arow0 = A + (size_t)ia * K;
            arow1 = A + (size_t)ib * K;
        } else {
            arow0 = A + (size_t)ma * K;
            arow1 = A + (size_t)mb * K;
        }
    }
    const int wk  = tid >> 5;
    const int wc4 = (tid & 31) * 4;

    ull acc[8][4];
#pragma unroll
    for (int r = 0; r < 8; ++r)
#pragma unroll
        for (int j = 0; j < 4; ++j) acc[r][j] = pack2(0.f, 0.f);

    const int nk = K / 16;
    float4 pa0, pa1, pw0, pw1;

    pa0 = *(const float4*)(arow0 + skq);
    pa1 = *(const float4*)(arow1 + skq);
    pw0 = *(const float4*)(W + (size_t)wk * CG + n0 + wc4);
    pw1 = *(const float4*)(W + (size_t)(wk + 8) * CG + n0 + wc4);

    As[0][skq + 0][sr] = pa0.x; As[0][skq + 1][sr] = pa0.y;
    As[0][skq + 2][sr] = pa0.z; As[0][skq + 3][sr] = pa0.w;
    As[0][skq + 0][sr + 64] = pa1.x; As[0][skq + 1][sr + 64] = pa1.y;
    As[0][skq + 2][sr + 64] = pa1.z; As[0][skq + 3][sr + 64] = pa1.w;
    *(float4*)&Ws[0][wk][wc4]     = pw0;
    *(float4*)&Ws[0][wk + 8][wc4] = pw1;
    __syncthreads();

    int p = 0;
    for (int kt = 0; kt < nk; ++kt) {
        const int k0n = (kt + 1) * 16;
        if (kt + 1 < nk) {
            pa0 = *(const float4*)(arow0 + k0n + skq);
            pa1 = *(const float4*)(arow1 + k0n + skq);
            pw0 = *(const float4*)(W + (size_t)(k0n + wk) * CG + n0 + wc4);
            pw1 = *(const float4*)(W + (size_t)(k0n + wk + 8) * CG + n0 + wc4);
        }
#pragma unroll
        for (int kk = 0; kk < 16; ++kk) {
            float4 a0 = *(const float4*)&As[p][kk][trow * 8];
            float4 a1 = *(const float4*)&As[p][kk][trow * 8 + 4];
            ulonglong2 b01 = *(const ulonglong2*)&Ws[p][kk][tcol * 8];
            ulonglong2 b23 = *(const ulonglong2*)&Ws[p][kk][tcol * 8 + 4];
            float av[8] = {a0.x, a0.y, a0.z, a0.w, a1.x, a1.y, a1.z, a1.w};
            ull bv[4] = {b01.x, b01.y, b23.x, b23.y};
#pragma unroll
            for (int r = 0; r < 8; ++r) {
                ull ad = pack2(av[r], av[r]);
#pragma unroll
                for (int j = 0; j < 4; ++j) acc[r][j] = ffma2(ad, bv[j], acc[r][j]);
            }
        }
        if (kt + 1 < nk) {
            int q = p ^ 1;
            As[q][skq + 0][sr] = pa0.x; As[q][skq + 1][sr] = pa0.y;
            As[q][skq + 2][sr] = pa0.z; As[q][skq + 3][sr] = pa0.w;
            As[q][skq + 0][sr + 64] = pa1.x; As[q][skq + 1][sr + 64] = pa1.y;
            As[q][skq + 2][sr + 64] = pa1.z; As[q][skq + 3][sr + 64] = pa1.w;
            *(float4*)&Ws[q][wk][wc4]     = pw0;
            *(float4*)&Ws[q][wk + 8][wc4] = pw1;
        }
        __syncthreads();
        p ^= 1;
    }

    float bv[8];
#pragma unroll
    for (int j = 0; j < 8; ++j) bv[j] = bias[n0 + tcol * 8 + j];
#pragma unroll
    for (int r = 0; r < 8; ++r) {
        float* crow = C + (size_t)(m0 + trow * 8 + r) * CG + n0 + tcol * 8;
        float2 t0 = unpack2(acc[r][0]), t1 = unpack2(acc[r][1]);
        float2 t2 = unpack2(acc[r][2]), t3 = unpack2(acc[r][3]);
        float4 v0 = {t0.x + bv[0], t0.y + bv[1], t1.x + bv[2], t1.y + bv[3]};
        float4 v1 = {t2.x + bv[4], t2.y + bv[5], t3.x + bv[6], t3.y + bv[7]};
        *(float4*)(crow)     = v0;
        *(float4*)(crow + 4) = v1;
    }
}

// ============================================================================
// Persistent LSTM layer, fma-bound design.
// 128 CTAs x 256 threads. CTA owns 8 hidden cols x 4 gates = 32 z-cols.
// U slice resident in smem for all 128 steps ([c][k] layout, XOR-swizzled).
// h streamed per step as cp.async double-buffered chunks ([b][k] layout).
// Thread = 2 cols x 8 batches x 512 k (k-split by 2, smem reduction).
// f32x2 packs k-parity: acc = {sum even-k, sum odd-k}.
// ============================================================================

// dynamic smem layout (floats):
//   sU  [32][1024]                 : 32768
//   sH  [2 buf][2 half][64 b][64 k]: 16384
//   sZp [2 half][64 b][33]         : 4224
#define SM_U   0
#define SM_H   32768
#define SM_ZP  49152
#define SM_FLOATS 53376
#define SM_BYTES (SM_FLOATS * 4)

__global__ __launch_bounds__(NTHR, 1) void lstm_kernel(
    const float* __restrict__ xz, const float* __restrict__ U,
    float* __restrict__ y, int y_ts, int y_bs,
    const float* __restrict__ h0, const float* __restrict__ c0,
    float* __restrict__ hOut, float* __restrict__ cOut)
{
    extern __shared__ float sm[];
    float* sU  = sm + SM_U;
    float* sHb = sm + SM_H;
    float* sZp = sm + SM_ZP;
    const unsigned sHbBytes = (unsigned)__cvta_generic_to_shared(sHb);

    const int tid = threadIdx.x;
    const int cta = blockIdx.x;
    const int hj  = cta * 8;

    // ---- init h, c (b-major: straight copy) ----
    for (int e = cta * NTHR + tid; e < CB * CH; e += NCTA * NTHR) {
        g_h[0][e] = h0[e];
        g_c[e]    = c0[e];
    }

    // ---- load U slice into smem, [c][k] with XOR swizzle on k bits 2..4 ----
    for (int idx = tid; idx < 32 * CH; idx += NTHR) {
        int c = idx & 31, k = idx >> 5;
        int gc = (c >> 3) * CH + hj + (c & 7);
        sU[c * CH + (k ^ (((c >> 1) & 7) << 2))] = U[(size_t)k * CG + gc];
    }

    // ---- thread decode ----
    const int lane  = tid & 31, w = tid >> 5;
    const int cgrp  = lane & 15;          // 16 col-pairs
    const int bsub  = lane >> 4;          // 0/1
    const int khalf = w >> 2;             // 0/1 : k in [khalf*512, +512)
    const int bpair = w & 3;              // 0..3
    const int bbase = bpair * 16 + bsub * 8;
    const int c0i   = cgrp * 2;
    const int uswz  = (cgrp & 7) << 2;
    const int hswz  = bsub << 2;

    const float* uRow0 = sU + c0i * CH;
    const float* uRow1 = uRow0 + CH;

    for (int t = 0; t < CT; ++t) {
        grid_sync();   // all CTAs wrote h[t]
        const float* hR = g_h[t & 1];

        // prefetch xz for epilogue (consumed ~10k cycles later)
        float xzv[8];
        {
            const float* xzt = xz + (size_t)t * CB * CG;
#pragma unroll
            for (int i = 0; i < 2; ++i) {
                int idx = tid + i * 256;
                int b = idx >> 3, hid = idx & 7;
                const float* p = xzt + (size_t)b * CG + hj + hid;
                xzv[i * 4 + 0] = p[0];
                xzv[i * 4 + 1] = p[CH];
                xzv[i * 4 + 2] = p[2 * CH];
                xzv[i * 4 + 3] = p[3 * CH];
            }
        }

        ull acc[16];
#pragma unroll
        for (int q = 0; q < 16; ++q) acc[q] = 0ull;

        // ---- issue chunk 0 ----
#pragma unroll
        for (int j = 0; j < 8; ++j) {
            int idx  = tid + j * 256;
            int half = idx >> 10;
            int b    = (idx >> 4) & 63;
            int k4   = (idx & 15) << 2;
            const float* g = hR + (size_t)b * CH + half * 512 + k4;
            unsigned dst = sHbBytes +
                ((half * 4096 + b * 64 + (k4 ^ (((b >> 3) & 1) << 2))) << 2);
            asm volatile("cp.async.cg.shared.global [%0],[%1],16;" :: "r"(dst), "l"(g));
        }
        asm volatile("cp.async.commit_group;");

        int buf = 0;
        for (int s = 0; s < 8; ++s) {
            if (s < 7) {   // issue chunk s+1 into other buffer
                int kb = (s + 1) * 64;
                int bo = (buf ^ 1) * 8192;
#pragma unroll
                for (int j = 0; j < 8; ++j) {
                    int idx  = tid + j * 256;
                    int half = idx >> 10;
                    int b    = (idx >> 4) & 63;
                    int k4   = (idx & 15) << 2;
                    const float* g = hR + (size_t)b * CH + half * 512 + kb + k4;
                    unsigned dst = sHbBytes +
                        ((bo + half * 4096 + b * 64 + (k4 ^ (((b >> 3) & 1) << 2))) << 2);
                    asm volatile("cp.async.cg.shared.global [%0],[%1],16;" :: "r"(dst), "l"(g));
                }
                asm volatile("cp.async.commit_group;");
                asm volatile("cp.async.wait_group 1;");
            } else {
                asm volatile("cp.async.wait_group 0;");
            }
            __syncthreads();   // chunk s visible to all threads

            // ---- compute chunk s: 64 k ----
            const float* hP = sHb + buf * 8192 + khalf * 4096 + bbase * 64;
            const int kb = khalf * 512 + s * 64;
#pragma unroll 4
            for (int g4 = 0; g4 < 16; ++g4) {
                int kk = g4 * 4;
                int ku = (kb + kk) ^ uswz;
                ulonglong2 u0 = *(const ulonglong2*)(uRow0 + ku);
                ulonglong2 u1 = *(const ulonglong2*)(uRow1 + ku);
                int kh = kk ^ hswz;
#pragma unroll
                for (int j = 0; j < 8; ++j) {
                    ulonglong2 hv = *(const ulonglong2*)(hP + j * 64 + kh);
                    acc[j]     = ffma2(hv.x, u0.x, acc[j]);
                    acc[j]     = ffma2(hv.y, u0.y, acc[j]);
                    acc[j + 8] = ffma2(hv.x, u1.x, acc[j + 8]);
                    acc[j + 8] = ffma2(hv.y, u1.y, acc[j + 8]);
                }
            }
            __syncthreads();   // all reads of buf done before it is re-filled
            buf ^= 1;
        }

        // ---- reduce k-parity + k-halves; gate math ----
#pragma unroll
        for (int cc = 0; cc < 2; ++cc)
#pragma unroll
            for (int j = 0; j < 8; ++j) {
                float2 v = unpack2(acc[cc * 8 + j]);
                sZp[(khalf * 64 + bbase + j) * 33 + c0i + cc] = v.x + v.y;
            }
        __syncthreads();

        float* hW = g_h[(t + 1) & 1];
#pragma unroll
        for (int i = 0; i < 2; ++i) {
            int idx = tid + i * 256;
            int b = idx >> 3, hid = idx & 7;
            const float* z0 = sZp + b * 33;
            const float* z1 = sZp + (64 + b) * 33;
            float zi = z0[hid]      + z1[hid]      + xzv[i * 4 + 0];
            float zf = z0[8 + hid]  + z1[8 + hid]  + xzv[i * 4 + 1];
            float zg = z0[16 + hid] + z1[16 + hid] + xzv[i * 4 + 2];
            float zo = z0[24 + hid] + z1[24 + hid] + xzv[i * 4 + 3];
            int off = b * CH + hj + hid;
            float cp = g_c[off];
            float cn = sigm_(zf) * cp + sigm_(zi) * tanhf_(zg);
            float hn = sigm_(zo) * tanhf_(cn);
            g_c[off] = cn;
            hW[off]  = hn;
            y[(size_t)t * y_ts + (size_t)b * y_bs + hj + hid] = hn;
            if (t == CT - 1) {
                hOut[off] = hn;
                cOut[off] = cn;
            }
        }
        // next grid_sync (top of loop) protects sZp/sH reuse
    }
}

// ============================================================================
extern "C" void kernel_launch(void* const* d_in, const int* in_sizes, int n_in,
                              void* d_out, int out_size)
{
    const int*   x   = (const int*)  d_in[0];
    const float* h01 = (const float*)d_in[1];
    const float* c01 = (const float*)d_in[2];
    const float* h02 = (const float*)d_in[3];
    const float* c02 = (const float*)d_in[4];
    const float* emb = (const float*)d_in[5];
    const float* W1  = (const float*)d_in[6];
    const float* U1  = (const float*)d_in[7];
    const float* b1  = (const float*)d_in[8];
    const float* W2  = (const float*)d_in[9];
    const float* U2  = (const float*)d_in[10];
    const float* b2  = (const float*)d_in[11];

    float* out = (float*)d_out;
    float* h1o = out + (size_t)CB * CT * CH;
    float* c1o = h1o + CB * CH;
    float* h2o = c1o + CB * CH;
    float* c2o = h2o + CB * CH;

    float *xzp, *y1p;
    cudaGetSymbolAddress((void**)&xzp, g_xz);
    cudaGetSymbolAddress((void**)&y1p, g_y1);

    static int smem_set = 0;
    if (!smem_set) {
        cudaFuncSetAttribute(lstm_kernel,
                             cudaFuncAttributeMaxDynamicSharedMemorySize, SM_BYTES);
        smem_set = 1;
    }

    dim3 gg(CG / 128, (CT * CB) / 128);   // (32, 64)

    // layer 1
    gemm_bias_kernel<true><<<gg, 256>>>(emb, x, W1, b1, xzp, CE);
    lstm_kernel<<<NCTA, NTHR, SM_BYTES>>>(xzp, U1, y1p, CB * CH, CH,
                                          h01, c01, h1o, c1o);
    // layer 2
    gemm_bias_kernel<false><<<gg, 256>>>(y1p, nullptr, W2, b2, xzp, CH);
    lstm_kernel<<<NCTA, NTHR, SM_BYTES>>>(xzp, U2, out, CH, CT * CH,
                                          h02, c02, h2o, c2o);
}

// round 7
// speedup vs baseline: 1.5667x; 1.0237x over previous
#include <cuda_runtime.h>
#include <cstdint>

typedef unsigned long long ull;

#define CB 64      // batch
#define CT 128     // time
#define CE 256     // embed
#define CH 1024    // hidden
#define CG 4096    // 4*H
#define NCTA 128   // persistent recurrence grid
#define LTHR 512   // lstm threads (16 warps)

// -------- scratch (device globals; no runtime allocation) --------
__device__ float g_xz[(size_t)CT * CB * CG];   // shared by layer1 & layer2
__device__ float g_y1[(size_t)CT * CB * CH];   // layer1 outputs [t][b][h]
__device__ float g_h[2][CB * CH];              // h state, b-major [b][k], double buffered
__device__ float g_c[CB * CH];                 // c state, b-major [b][k]
__device__ unsigned g_bar;                     // monotonic grid-barrier counter

// -------- packed fp32 helpers --------
__device__ __forceinline__ ull ffma2(ull a, ull b, ull c) {
    ull d; asm("fma.rn.f32x2 %0,%1,%2,%3;" : "=l"(d) : "l"(a), "l"(b), "l"(c)); return d;
}
__device__ __forceinline__ ull pack2(float x, float y) {
    ull d; asm("mov.b64 %0,{%1,%2};" : "=l"(d) : "f"(x), "f"(y)); return d;
}
__device__ __forceinline__ float2 unpack2(ull v) {
    float2 r; asm("mov.b64 {%0,%1},%2;" : "=f"(r.x), "=f"(r.y) : "l"(v)); return r;
}

__device__ __forceinline__ float sigm_(float x)  { return __fdividef(1.f, 1.f + __expf(-x)); }
__device__ __forceinline__ float tanhf_(float x) { return __fdividef(2.f, 1.f + __expf(-2.f * x)) - 1.f; }

// Monotonic-counter grid barrier (no reset race; safe across graph replays).
__device__ __forceinline__ void grid_sync() {
    __threadfence();
    __syncthreads();
    if (threadIdx.x == 0) {
        unsigned old = atomicAdd(&g_bar, 1u);
        unsigned target = (old / NCTA + 1u) * NCTA;
        while (*((volatile unsigned*)&g_bar) < target) {}
        __threadfence();
    }
    __syncthreads();
}

// ============================================================================
// GEMM: C[M, 4096] = A[M,K] @ W[K,4096] + bias, optional row gather (emb).
// ============================================================================
template <bool GATHER>
__global__ __launch_bounds__(256) void gemm_bias_kernel(
    const float* __restrict__ A, const int* __restrict__ xidx,
    const float* __restrict__ W, const float* __restrict__ bias,
    float* __restrict__ C, int K)
{
    __shared__ float As[2][16][132];
    __shared__ float Ws[2][16][128];

    const int tid  = threadIdx.x;
    const int n0   = blockIdx.x * 128;
    const int m0   = blockIdx.y * 128;
    const int trow = tid >> 4;
    const int tcol = tid & 15;

    const int sr  = tid >> 2;
    const int skq = (tid & 3) * 4;
    const float* arow0;
    const float* arow1;
    {
        int ma = m0 + sr, mb = m0 + sr + 64;
        if (GATHER) {
            int ia = xidx[(ma % CB) * CT + (ma / CB)];
            int ib = xidx[(mb % CB) * CT + (mb / CB)];
            arow0 = A + (size_t)ia * K;
            arow1 = A + (size_t)ib * K;
        } else {
            arow0 = A + (size_t)ma * K;
            arow1 = A + (size_t)mb * K;
        }
    }
    const int wk  = tid >> 5;
    const int wc4 = (tid & 31) * 4;

    ull acc[8][4];
#pragma unroll
    for (int r = 0; r < 8; ++r)
#pragma unroll
        for (int j = 0; j < 4; ++j) acc[r][j] = pack2(0.f, 0.f);

    const int nk = K / 16;
    float4 pa0, pa1, pw0, pw1;

    pa0 = *(const float4*)(arow0 + skq);
    pa1 = *(const float4*)(arow1 + skq);
    pw0 = *(const float4*)(W + (size_t)wk * CG + n0 + wc4);
    pw1 = *(const float4*)(W + (size_t)(wk + 8) * CG + n0 + wc4);

    As[0][skq + 0][sr] = pa0.x; As[0][skq + 1][sr] = pa0.y;
    As[0][skq + 2][sr] = pa0.z; As[0][skq + 3][sr] = pa0.w;
    As[0][skq + 0][sr + 64] = pa1.x; As[0][skq + 1][sr + 64] = pa1.y;
    As[0][skq + 2][sr + 64] = pa1.z; As[0][skq + 3][sr + 64] = pa1.w;
    *(float4*)&Ws[0][wk][wc4]     = pw0;
    *(float4*)&Ws[0][wk + 8][wc4] = pw1;
    __syncthreads();

    int p = 0;
    for (int kt = 0; kt < nk; ++kt) {
        const int k0n = (kt + 1) * 16;
        if (kt + 1 < nk) {
            pa0 = *(const float4*)(arow0 + k0n + skq);
            pa1 = *(const float4*)(arow1 + k0n + skq);
            pw0 = *(const float4*)(W + (size_t)(k0n + wk) * CG + n0 + wc4);
            pw1 = *(const float4*)(W + (size_t)(k0n + wk + 8) * CG + n0 + wc4);
        }
#pragma unroll
        for (int kk = 0; kk < 16; ++kk) {
            float4 a0 = *(const float4*)&As[p][kk][trow * 8];
            float4 a1 = *(const float4*)&As[p][kk][trow * 8 + 4];
            ulonglong2 b01 = *(const ulonglong2*)&Ws[p][kk][tcol * 8];
            ulonglong2 b23 = *(const ulonglong2*)&Ws[p][kk][tcol * 8 + 4];
            float av[8] = {a0.x, a0.y, a0.z, a0.w, a1.x, a1.y, a1.z, a1.w};
            ull bv[4] = {b01.x, b01.y, b23.x, b23.y};
#pragma unroll
            for (int r = 0; r < 8; ++r) {
                ull ad = pack2(av[r], av[r]);
#pragma unroll
                for (int j = 0; j < 4; ++j) acc[r][j] = ffma2(ad, bv[j], acc[r][j]);
            }
        }
        if (kt + 1 < nk) {
            int q = p ^ 1;
            As[q][skq + 0][sr] = pa0.x; As[q][skq + 1][sr] = pa0.y;
            As[q][skq + 2][sr] = pa0.z; As[q][skq + 3][sr] = pa0.w;
            As[q][skq + 0][sr + 64] = pa1.x; As[q][skq + 1][sr + 64] = pa1.y;
            As[q][skq + 2][sr + 64] = pa1.z; As[q][skq + 3][sr + 64] = pa1.w;
            *(float4*)&Ws[q][wk][wc4]     = pw0;
            *(float4*)&Ws[q][wk + 8][wc4] = pw1;
        }
        __syncthreads();
        p ^= 1;
    }

    float bv[8];
#pragma unroll
    for (int j = 0; j < 8; ++j) bv[j] = bias[n0 + tcol * 8 + j];
#pragma unroll
    for (int r = 0; r < 8; ++r) {
        float* crow = C + (size_t)(m0 + trow * 8 + r) * CG + n0 + tcol * 8;
        float2 t0 = unpack2(acc[r][0]), t1 = unpack2(acc[r][1]);
        float2 t2 = unpack2(acc[r][2]), t3 = unpack2(acc[r][3]);
        float4 v0 = {t0.x + bv[0], t0.y + bv[1], t1.x + bv[2], t1.y + bv[3]};
        float4 v1 = {t2.x + bv[4], t2.y + bv[5], t3.x + bv[6], t3.y + bv[7]};
        *(float4*)(crow)     = v0;
        *(float4*)(crow + 4) = v1;
    }
}

// ============================================================================
// Persistent LSTM layer — 512 threads / 16 warps for latency coverage.
// CTA owns 8 hidden cols x 4 gates = 32 z-cols. U resident in smem (128 KB).
// h streamed per step via cp.async double-buffered 128k-chunks [64b][128k].
// Warp w: kq = w>>2 (k-quarter, 32k slice per chunk), bpair = w&3.
// Thread: 2 cols x 8 batches x 256 k; f32x2 packs k-parity.
// 4-way k-partials reduced through sZp[4][64][33].
// ============================================================================

// dynamic smem layout (floats):
//   sU  [32][1024]          : 32768
//   sH  [2 buf][64 b][128 k]: 16384
//   sZp [4][64][33]         : 8448
#define SM_U   0
#define SM_H   32768
#define SM_ZP  49152
#define SM_FLOATS 57600
#define SM_BYTES (SM_FLOATS * 4)

__global__ __launch_bounds__(LTHR, 1) void lstm_kernel(
    const float* __restrict__ xz, const float* __restrict__ U,
    float* __restrict__ y, int y_ts, int y_bs,
    const float* __restrict__ h0, const float* __restrict__ c0,
    float* __restrict__ hOut, float* __restrict__ cOut)
{
    extern __shared__ float sm[];
    float* sU  = sm + SM_U;
    float* sHb = sm + SM_H;
    float* sZp = sm + SM_ZP;
    const unsigned sHbBytes = (unsigned)__cvta_generic_to_shared(sHb);

    const int tid = threadIdx.x;
    const int cta = blockIdx.x;
    const int hj  = cta * 8;

    // ---- init h, c (b-major: straight copy) ----
    for (int e = cta * LTHR + tid; e < CB * CH; e += NCTA * LTHR) {
        g_h[0][e] = h0[e];
        g_c[e]    = c0[e];
    }

    // ---- load U slice into smem, [c][k], XOR swizzle on k bits 2..4 ----
    for (int idx = tid; idx < 32 * CH; idx += LTHR) {
        int c = idx & 31, k = idx >> 5;
        int gc = (c >> 3) * CH + hj + (c & 7);
        sU[c * CH + (k ^ (((c >> 1) & 7) << 2))] = U[(size_t)k * CG + gc];
    }

    // ---- thread decode ----
    const int lane  = tid & 31, w = tid >> 5;
    const int cgrp  = lane & 15;          // 16 col-pairs
    const int bsub  = lane >> 4;          // 0/1
    const int kq    = w >> 2;             // 0..3 : 32k slice within each chunk
    const int bpair = w & 3;              // 0..3
    const int bbase = bpair * 16 + bsub * 8;
    const int c0i   = cgrp * 2;
    const int uswz  = (cgrp & 7) << 2;
    const int hswz  = bsub << 2;

    const float* uRow0 = sU + c0i * CH;
    const float* uRow1 = uRow0 + CH;

    // epilogue decode (1 (b,hid) per thread)
    const int eb = tid >> 3, ehid = tid & 7;

    for (int t = 0; t < CT; ++t) {
        grid_sync();   // all CTAs wrote h[t]
        const float* hR = g_h[t & 1];

        // prefetch xz for epilogue
        float xzv[4];
        {
            const float* p = xz + (size_t)t * CB * CG + (size_t)eb * CG + hj + ehid;
            xzv[0] = p[0];
            xzv[1] = p[CH];
            xzv[2] = p[2 * CH];
            xzv[3] = p[3 * CH];
        }

        ull acc[16];
#pragma unroll
        for (int q = 0; q < 16; ++q) acc[q] = 0ull;

        // ---- issue chunk 0 (128 k for all 64 b = 32 KB) ----
#pragma unroll
        for (int j = 0; j < 4; ++j) {
            int idx = tid + j * LTHR;
            int b   = idx >> 5;
            int k4  = (idx & 31) << 2;
            const float* g = hR + (size_t)b * CH + k4;
            unsigned dst = sHbBytes +
                ((b * 128 + (k4 ^ (((b >> 3) & 1) << 2))) << 2);
            asm volatile("cp.async.cg.shared.global [%0],[%1],16;" :: "r"(dst), "l"(g));
        }
        asm volatile("cp.async.commit_group;");

        int buf = 0;
        for (int s = 0; s < 8; ++s) {
            if (s < 7) {   // issue chunk s+1 into other buffer
                int kb = (s + 1) * 128;
                int bo = (buf ^ 1) * 8192;
#pragma unroll
                for (int j = 0; j < 4; ++j) {
                    int idx = tid + j * LTHR;
                    int b   = idx >> 5;
                    int k4  = (idx & 31) << 2;
                    const float* g = hR + (size_t)b * CH + kb + k4;
                    unsigned dst = sHbBytes +
                        ((bo + b * 128 + (k4 ^ (((b >> 3) & 1) << 2))) << 2);
                    asm volatile("cp.async.cg.shared.global [%0],[%1],16;" :: "r"(dst), "l"(g));
                }
                asm volatile("cp.async.commit_group;");
                asm volatile("cp.async.wait_group 1;");
            } else {
                asm volatile("cp.async.wait_group 0;");
            }
            __syncthreads();   // chunk s visible to all threads

            // ---- compute: this warp's 32k slice of chunk s ----
            const float* hP = sHb + buf * 8192 + bbase * 128;
            const int kgl = s * 128 + kq * 32;   // global k base of slice
            const int klo = kq * 32;             // k base within chunk row
#pragma unroll 4
            for (int g4 = 0; g4 < 8; ++g4) {
                int kk = g4 * 4;
                int ku = (kgl + kk) ^ uswz;
                ulonglong2 u0 = *(const ulonglong2*)(uRow0 + ku);
                ulonglong2 u1 = *(const ulonglong2*)(uRow1 + ku);
                int kh = (klo + kk) ^ hswz;
#pragma unroll
                for (int j = 0; j < 8; ++j) {
                    ulonglong2 hv = *(const ulonglong2*)(hP + j * 128 + kh);
                    acc[j]     = ffma2(hv.x, u0.x, acc[j]);
                    acc[j]     = ffma2(hv.y, u0.y, acc[j]);
                    acc[j + 8] = ffma2(hv.x, u1.x, acc[j + 8]);
                    acc[j + 8] = ffma2(hv.y, u1.y, acc[j + 8]);
                }
            }
            __syncthreads();   // all reads of buf done before refill
            buf ^= 1;
        }

        // ---- reduce k-parity, write 4-way partials ----
#pragma unroll
        for (int cc = 0; cc < 2; ++cc)
#pragma unroll
            for (int j = 0; j < 8; ++j) {
                float2 v = unpack2(acc[cc * 8 + j]);
                sZp[(kq * 64 + bbase + j) * 33 + c0i + cc] = v.x + v.y;
            }
        __syncthreads();

        // ---- gate math: 1 (b,hid) per thread ----
        float* hW = g_h[(t + 1) & 1];
        {
            const float* z0 = sZp + eb * 33;
            const float* z1 = z0 + 64 * 33;
            const float* z2 = z1 + 64 * 33;
            const float* z3 = z2 + 64 * 33;
            float zi = z0[ehid]      + z1[ehid]      + z2[ehid]      + z3[ehid]      + xzv[0];
            float zf = z0[8 + ehid]  + z1[8 + ehid]  + z2[8 + ehid]  + z3[8 + ehid]  + xzv[1];
            float zg = z0[16 + ehid] + z1[16 + ehid] + z2[16 + ehid] + z3[16 + ehid] + xzv[2];
            float zo = z0[24 + ehid] + z1[24 + ehid] + z2[24 + ehid] + z3[24 + ehid] + xzv[3];
            int off = eb * CH + hj + ehid;
            float cp = g_c[off];
            float cn = sigm_(zf) * cp + sigm_(zi) * tanhf_(zg);
            float hn = sigm_(zo) * tanhf_(cn);
            g_c[off] = cn;
            hW[off]  = hn;
            y[(size_t)t * y_ts + (size_t)eb * y_bs + hj + ehid] = hn;
            if (t == CT - 1) {
                hOut[off] = hn;
                cOut[off] = cn;
            }
        }
        // next grid_sync (top of loop) protects sZp/sHb reuse
    }
}

// ============================================================================
extern "C" void kernel_launch(void* const* d_in, const int* in_sizes, int n_in,
                              void* d_out, int out_size)
{
    const int*   x   = (const int*)  d_in[0];
    const float* h01 = (const float*)d_in[1];
    const float* c01 = (const float*)d_in[2];
    const float* h02 = (const float*)d_in[3];
    const float* c02 = (const float*)d_in[4];
    const float* emb = (const float*)d_in[5];
    const float* W1  = (const float*)d_in[6];
    const float* U1  = (const float*)d_in[7];
    const float* b1  = (const float*)d_in[8];
    const float* W2  = (const float*)d_in[9];
    const float* U2  = (const float*)d_in[10];
    const float* b2  = (const float*)d_in[11];

    float* out = (float*)d_out;
    float* h1o = out + (size_t)CB * CT * CH;
    float* c1o = h1o + CB * CH;
    float* h2o = c1o + CB * CH;
    float* c2o = h2o + CB * CH;

    float *xzp, *y1p;
    cudaGetSymbolAddress((void**)&xzp, g_xz);
    cudaGetSymbolAddress((void**)&y1p, g_y1);

    static int smem_set = 0;
    if (!smem_set) {
        cudaFuncSetAttribute(lstm_kernel,
                             cudaFuncAttributeMaxDynamicSharedMemorySize, SM_BYTES);
        smem_set = 1;
    }

    dim3 gg(CG / 128, (CT * CB) / 128);   // (32, 64)

    // layer 1
    gemm_bias_kernel<true><<<gg, 256>>>(emb, x, W1, b1, xzp, CE);
    lstm_kernel<<<NCTA, LTHR, SM_BYTES>>>(xzp, U1, y1p, CB * CH, CH,
                                          h01, c01, h1o, c1o);
    // layer 2
    gemm_bias_kernel<false><<<gg, 256>>>(y1p, nullptr, W2, b2, xzp, CH);
    lstm_kernel<<<NCTA, LTHR, SM_BYTES>>>(xzp, U2, out, CH, CT * CH,
                                          h02, c02, h2o, c2o);
}

// round 13
// speedup vs baseline: 2.3300x; 1.4872x over previous
#include <cuda_runtime.h>
#include <cuda_bf16.h>
#include <cstdint>

typedef unsigned long long ull;

#define CB 64      // batch
#define CT 128     // time
#define CE 256     // embed
#define CH 1024    // hidden
#define CG 4096    // 4*H
#define NCTA 128   // persistent recurrence grid
#define LTHR 512   // lstm threads (16 warps)

// -------- scratch (device globals; no runtime allocation) --------
__device__ float g_xz[(size_t)CT * CB * CG];   // shared by layer1 & layer2
__device__ float g_y1[(size_t)CT * CB * CH];   // layer1 outputs [t][b][h]
__device__ __align__(16) unsigned short g_hbf[2][2][CB * CH]; // [buf][hi/lo][b*CH+k] bf16
__device__ unsigned g_bar;                     // monotonic grid-barrier counter

// -------- packed fp32 helpers (GEMM) --------
__device__ __forceinline__ ull ffma2(ull a, ull b, ull c) {
    ull d; asm("fma.rn.f32x2 %0,%1,%2,%3;" : "=l"(d) : "l"(a), "l"(b), "l"(c)); return d;
}
__device__ __forceinline__ ull pack2(float x, float y) {
    ull d; asm("mov.b64 %0,{%1,%2};" : "=l"(d) : "f"(x), "f"(y)); return d;
}
__device__ __forceinline__ float2 unpack2(ull v) {
    float2 r; asm("mov.b64 {%0,%1},%2;" : "=f"(r.x), "=f"(r.y) : "l"(v)); return r;
}

__device__ __forceinline__ float sigm_(float x)  { return __fdividef(1.f, 1.f + __expf(-x)); }
__device__ __forceinline__ float tanhf_(float x) { return __fdividef(2.f, 1.f + __expf(-2.f * x)) - 1.f; }

// Monotonic-counter grid barrier (no reset race; safe across graph replays).
__device__ __forceinline__ void grid_sync() {
    __threadfence();
    __syncthreads();
    if (threadIdx.x == 0) {
        unsigned old = atomicAdd(&g_bar, 1u);
        unsigned target = (old / NCTA + 1u) * NCTA;
        while (*((volatile unsigned*)&g_bar) < target) {}
        __threadfence();
    }
    __syncthreads();
}

// -------- warp MMA helpers (baseline PTX: works on sm_103 plain) --------
__device__ __forceinline__ void ldsm4(unsigned& r0, unsigned& r1, unsigned& r2, unsigned& r3,
                                      unsigned addr) {
    asm volatile("ldmatrix.sync.aligned.m8n8.x4.shared.b16 {%0,%1,%2,%3},[%4];"
                 : "=r"(r0), "=r"(r1), "=r"(r2), "=r"(r3) : "r"(addr));
}
#define MMA16816(d, a, b0, b1)                                              \
    asm volatile("mma.sync.aligned.m16n8k16.row.col.f32.bf16.bf16.f32 "     \
        "{%0,%1,%2,%3},{%4,%5,%6,%7},{%8,%9},{%0,%1,%2,%3};"                \
        : "+f"((d)[0]), "+f"((d)[1]), "+f"((d)[2]), "+f"((d)[3])            \
        : "r"((a)[0]), "r"((a)[1]), "r"((a)[2]), "r"((a)[3]),               \
          "r"(b0), "r"(b1))

// ============================================================================
// GEMM: C[M, 4096] = A[M,K] @ W[K,4096] + bias, optional row gather (emb).
// (unchanged — proven)
// ============================================================================
template <bool GATHER>
__global__ __launch_bounds__(256) void gemm_bias_kernel(
    const float* __restrict__ A, const int* __restrict__ xidx,
    const float* __restrict__ W, const float* __restrict__ bias,
    float* __restrict__ C, int K)
{
    __shared__ float As[2][16][132];
    __shared__ float Ws[2][16][128];

    const int tid  = threadIdx.x;
    const int n0   = blockIdx.x * 128;
    const int m0   = blockIdx.y * 128;
    const int trow = tid >> 4;
    const int tcol = tid & 15;

    const int sr  = tid >> 2;
    const int skq = (tid & 3) * 4;
    const float* arow0;
    const float* arow1;
    {
        int ma = m0 + sr, mb = m0 + sr + 64;
        if (GATHER) {
            int ia = xidx[(ma % CB) * CT + (ma / CB)];
            int ib = xidx[(mb % CB) * CT + (mb / CB)];
            arow0 = A + (size_t)ia * K;
            arow1 = A + (size_t)ib * K;
        } else {
            arow0 = A + (size_t)ma * K;
            arow1 = A + (size_t)mb * K;
        }
    }
    const int wk  = tid >> 5;
    const int wc4 = (tid & 31) * 4;

    ull acc[8][4];
#pragma unroll
    for (int r = 0; r < 8; ++r)
#pragma unroll
        for (int j = 0; j < 4; ++j) acc[r][j] = pack2(0.f, 0.f);

    const int nk = K / 16;
    float4 pa0, pa1, pw0, pw1;

    pa0 = *(const float4*)(arow0 + skq);
    pa1 = *(const float4*)(arow1 + skq);
    pw0 = *(const float4*)(W + (size_t)wk * CG + n0 + wc4);
    pw1 = *(const float4*)(W + (size_t)(wk + 8) * CG + n0 + wc4);

    As[0][skq + 0][sr] = pa0.x; As[0][skq + 1][sr] = pa0.y;
    As[0][skq + 2][sr] = pa0.z; As[0][skq + 3][sr] = pa0.w;
    As[0][skq + 0][sr + 64] = pa1.x; As[0][skq + 1][sr + 64] = pa1.y;
    As[0][skq + 2][sr + 64] = pa1.z; As[0][skq + 3][sr + 64] = pa1.w;
    *(float4*)&Ws[0][wk][wc4]     = pw0;
    *(float4*)&Ws[0][wk + 8][wc4] = pw1;
    __syncthreads();

    int p = 0;
    for (int kt = 0; kt < nk; ++kt) {
        const int k0n = (kt + 1) * 16;
        if (kt + 1 < nk) {
            pa0 = *(const float4*)(arow0 + k0n + skq);
            pa1 = *(const float4*)(arow1 + k0n + skq);
            pw0 = *(const float4*)(W + (size_t)(k0n + wk) * CG + n0 + wc4);
            pw1 = *(const float4*)(W + (size_t)(k0n + wk + 8) * CG + n0 + wc4);
        }
#pragma unroll
        for (int kk = 0; kk < 16; ++kk) {
            float4 a0 = *(const float4*)&As[p][kk][trow * 8];
            float4 a1 = *(const float4*)&As[p][kk][trow * 8 + 4];
            ulonglong2 b01 = *(const ulonglong2*)&Ws[p][kk][tcol * 8];
            ulonglong2 b23 = *(const ulonglong2*)&Ws[p][kk][tcol * 8 + 4];
            float av[8] = {a0.x, a0.y, a0.z, a0.w, a1.x, a1.y, a1.z, a1.w};
            ull bv[4] = {b01.x, b01.y, b23.x, b23.y};
#pragma unroll
            for (int r = 0; r < 8; ++r) {
                ull ad = pack2(av[r], av[r]);
#pragma unroll
                for (int j = 0; j < 4; ++j) acc[r][j] = ffma2(ad, bv[j], acc[r][j]);
            }
        }
        if (kt + 1 < nk) {
            int q = p ^ 1;
            As[q][skq + 0][sr] = pa0.x; As[q][skq + 1][sr] = pa0.y;
            As[q][skq + 2][sr] = pa0.z; As[q][skq + 3][sr] = pa0.w;
            As[q][skq + 0][sr + 64] = pa1.x; As[q][skq + 1][sr + 64] = pa1.y;
            As[q][skq + 2][sr + 64] = pa1.z; As[q][skq + 3][sr + 64] = pa1.w;
            *(float4*)&Ws[q][wk][wc4]     = pw0;
            *(float4*)&Ws[q][wk + 8][wc4] = pw1;
        }
        __syncthreads();
        p ^= 1;
    }

    float bv[8];
#pragma unroll
    for (int j = 0; j < 8; ++j) bv[j] = bias[n0 + tcol * 8 + j];
#pragma unroll
    for (int r = 0; r < 8; ++r) {
        float* crow = C + (size_t)(m0 + trow * 8 + r) * CG + n0 + tcol * 8;
        float2 t0 = unpack2(acc[r][0]), t1 = unpack2(acc[r][1]);
        float2 t2 = unpack2(acc[r][2]), t3 = unpack2(acc[r][3]);
        float4 v0 = {t0.x + bv[0], t0.y + bv[1], t1.x + bv[2], t1.y + bv[3]};
        float4 v1 = {t2.x + bv[4], t2.y + bv[5], t3.x + bv[6], t3.y + bv[7]};
        *(float4*)(crow)     = v0;
        *(float4*)(crow + 4) = v1;
    }
}

// ============================================================================
// Persistent LSTM layer on warp-level MMA (mma.sync bf16, SIMT tensor path).
//
// Per CTA: z[64 b][32 c] via D[128 m][64 n]:
//   A rows  0-63 = h_hi bf16, 64-127 = h_lo (residual);
//   B cols  0-31 = U_hi,      32-63  = U_lo.
//   z[b][c] = D[b][c] + D[b][c+32] + D[b+64][c] + D[b+64][c+32]  (full fp32-class)
// U resident in smem (128 KB bf16, XOR-swizzled rows for ldmatrix).
// h streamed as 16 cp.async double-buffered chunks [128 m][64 k] (16 KB).
// 16 warps = 4 m-pairs x 2 n-halves x 2 k-halves; 8 tiles (m16n8) per warp,
// register accumulation over full k; 2-phase smem reduction of k-halves.
// ============================================================================

// smem layout (bytes):
#define SMW_U 0                         // U hi/lo [64 n][1024 k] bf16: 131072
#define SMW_A 131072                    // 2 x A chunk [128][64] bf16: 32768
#define SMW_Z (131072 + 32768)          // D partials [128][72] f32: 36864
#define SMW_X (SMW_Z + 36864)           // xz stage [64][36] f32: 9216
#define SMW_BYTES (SMW_X + 9216)        // 209920

__device__ __forceinline__ void load_chunkW(unsigned dstBase, int hbuf, int kb, int tid) {
#pragma unroll
    for (int j = 0; j < 2; ++j) {
        int idx = tid + j * LTHR;        // 0..1023
        int m   = idx >> 3;              // 0..127 (0-63 hi, 64-127 lo)
        int g8  = idx & 7;               // 16B granule within 128B row
        int part = m >> 6, b = m & 63;
        const unsigned short* src = &g_hbf[hbuf][part][b * CH + kb + g8 * 8];
        unsigned dst = dstBase + (unsigned)(m * 128 + ((g8 * 16) ^ ((m & 7) << 4)));
        asm volatile("cp.async.cg.shared.global [%0],[%1],16;" :: "r"(dst), "l"(src));
    }
}

__global__ __launch_bounds__(LTHR, 1) void lstm_kernel(
    const float* __restrict__ xz, const float* __restrict__ U,
    float* __restrict__ y, int y_ts, int y_bs,
    const float* __restrict__ h0, const float* __restrict__ c0,
    float* __restrict__ hOut, float* __restrict__ cOut)
{
    extern __shared__ char smc[];
    const unsigned sb = (unsigned)__cvta_generic_to_shared(smc);
    float* sZ = (float*)(smc + SMW_Z);
    float* sX = (float*)(smc + SMW_X);

    const int tid  = threadIdx.x;
    const int cta  = blockIdx.x;
    const int hj   = cta * 8;
    const int lane = tid & 31, w = tid >> 5;
    const int mp = w & 3, nh = (w >> 2) & 1, kh = w >> 3;

    // ---- init h-state bf16 hi/lo (all CTAs cooperate) ----
    for (int e = cta * LTHR + tid; e < CB * CH; e += NCTA * LTHR) {
        float v = h0[e];
        __nv_bfloat16 hi = __float2bfloat16(v);
        __nv_bfloat16 lo = __float2bfloat16(v - __bfloat162float(hi));
        g_hbf[0][0][e] = __bfloat16_as_ushort(hi);
        g_hbf[0][1][e] = __bfloat16_as_ushort(lo);
    }

    // ---- U slice -> smem [64 n][1024 k] bf16, rows 0-31 hi, 32-63 lo ----
    for (int idx = tid; idx < 64 * CH; idx += LTHR) {
        int n = idx & 63, k = idx >> 6;
        int c = n & 31;
        int gc = (c >> 3) * CH + hj + (c & 7);
        float v = U[(size_t)k * CG + gc];
        __nv_bfloat16 hi = __float2bfloat16(v);
        __nv_bfloat16 val = (n < 32) ? hi : __float2bfloat16(v - __bfloat162float(hi));
        unsigned byt = (unsigned)(n * 2048 + ((k * 2) ^ ((n & 7) << 4)));
        *(__nv_bfloat16*)(smc + SMW_U + byt) = val;
    }

    // ---- c state in registers (threads 0..63 own batch row eb) ----
    const int eb = tid;
    float creg[8];
    if (tid < 64) {
#pragma unroll
        for (int j = 0; j < 8; ++j) creg[j] = c0[eb * CH + hj + j];
    }
    __syncthreads();

    // ---- per-lane ldmatrix address components ----
    const int rowA = 32 * mp + (lane & 7) + 8 * ((lane >> 3) & 1);
    const unsigned aB1 = sb + SMW_A + (unsigned)(rowA * 128);
    const unsigned aB2 = aB1 + 16 * 128;
    const unsigned mx  = (unsigned)((rowA & 7) << 4);
    const unsigned kh16A = (unsigned)(((lane >> 4) & 1) * 16);

    const int nB = 32 * nh + ((lane >> 4) & 1) * 8 + (lane & 7);
    const unsigned bB1 = sb + SMW_U + (unsigned)(nB * 2048);
    const unsigned bB2 = bB1 + 16 * 2048;
    const unsigned nx  = (unsigned)((nB & 7) << 4);
    const unsigned kplusB = (unsigned)(((lane >> 3) & 1) * 16);

    // xz cp.async decode
    const int xb = tid >> 3, xseg = tid & 7;
    const int xgate = xseg >> 1, xhalf = xseg & 1;

    for (int t = 0; t < CT; ++t) {
        grid_sync();   // all CTAs published h[t]
        const int hbuf = t & 1;

        float acc[32];
#pragma unroll
        for (int q = 0; q < 32; ++q) acc[q] = 0.f;

        // group0: xz stage + chunk0 ; group1: chunk1
        {
            const float* src = xz + (size_t)t * CB * CG + (size_t)xb * CG
                               + xgate * CH + hj + xhalf * 4;
            unsigned dst = sb + SMW_X + (unsigned)((xb * 36 + xgate * 8 + xhalf * 4) * 4);
            asm volatile("cp.async.cg.shared.global [%0],[%1],16;" :: "r"(dst), "l"(src));
        }
        load_chunkW(sb + SMW_A, hbuf, 0, tid);
        asm volatile("cp.async.commit_group;");
        load_chunkW(sb + SMW_A + 16384, hbuf, 64, tid);
        asm volatile("cp.async.commit_group;");

        for (int ch = 0; ch < 16; ++ch) {
            if (ch < 15) asm volatile("cp.async.wait_group 1;" ::: "memory");
            else         asm volatile("cp.async.wait_group 0;" ::: "memory");
            __syncthreads();   // chunk ch visible

            const unsigned abb = (unsigned)((ch & 1) * 16384);
#pragma unroll
            for (int ks = 0; ks < 2; ++ks) {
                const int kl = kh * 2 + ks;                  // kstep within chunk
                const unsigned kofsA = (unsigned)(kl * 32 + kh16A) ^ mx;
                unsigned a0[4], a1[4], b0[4], b1[4];
                ldsm4(a0[0], a0[1], a0[2], a0[3], aB1 + abb + kofsA);
                ldsm4(a1[0], a1[1], a1[2], a1[3], aB2 + abb + kofsA);
                const unsigned kB = (unsigned)(ch * 128 + kl * 32 + kplusB) ^ nx;
                ldsm4(b0[0], b0[1], b0[2], b0[3], bB1 + kB);
                ldsm4(b1[0], b1[1], b1[2], b1[3], bB2 + kB);
                MMA16816(acc + 0,  a0, b0[0], b0[1]);
                MMA16816(acc + 4,  a0, b0[2], b0[3]);
                MMA16816(acc + 8,  a0, b1[0], b1[1]);
                MMA16816(acc + 12, a0, b1[2], b1[3]);
                MMA16816(acc + 16, a1, b0[0], b0[1]);
                MMA16816(acc + 20, a1, b0[2], b0[3]);
                MMA16816(acc + 24, a1, b1[0], b1[1]);
                MMA16816(acc + 28, a1, b1[2], b1[3]);
            }
            __syncthreads();   // reads done before buffer refill
            if (ch + 2 < 16) {
                load_chunkW(sb + SMW_A + (unsigned)((ch & 1) * 16384), hbuf,
                            (ch + 2) * 64, tid);
                asm volatile("cp.async.commit_group;");
            }
        }

        // ---- 2-phase k-half reduction into sZ[128][72] ----
        const int g   = lane >> 2;
        const int tg2 = (lane & 3) * 2;
        if (kh == 0) {
#pragma unroll
            for (int mt = 0; mt < 2; ++mt)
#pragma unroll
                for (int nt = 0; nt < 4; ++nt) {
                    const float* a = acc + (mt * 4 + nt) * 4;
                    float* p = sZ + (32 * mp + mt * 16 + g) * 72 + 32 * nh + nt * 8 + tg2;
                    *(float2*)p            = make_float2(a[0], a[1]);
                    *(float2*)(p + 8 * 72) = make_float2(a[2], a[3]);
                }
        }
        __syncthreads();
        if (kh == 1) {
#pragma unroll
            for (int mt = 0; mt < 2; ++mt)
#pragma unroll
                for (int nt = 0; nt < 4; ++nt) {
                    const float* a = acc + (mt * 4 + nt) * 4;
                    float* p = sZ + (32 * mp + mt * 16 + g) * 72 + 32 * nh + nt * 8 + tg2;
                    float2 v0 = *(float2*)p;
                    float2 v1 = *(float2*)(p + 8 * 72);
                    *(float2*)p            = make_float2(v0.x + a[0], v0.y + a[1]);
                    *(float2*)(p + 8 * 72) = make_float2(v1.x + a[2], v1.y + a[3]);
                }
        }
        __syncthreads();

        // ---- gates: threads 0..63, quadrant sums + xz ----
        if (tid < 64) {
            const float* z0 = sZ + eb * 72;          // h_hi rows
            const float* z1 = sZ + (eb + 64) * 72;   // h_lo rows
            const float* xr = sX + eb * 36;
            float hn8[8];
#pragma unroll
            for (int hd = 0; hd < 8; ++hd) {
                float zi = z0[hd]      + z0[32 + hd] + z1[hd]      + z1[32 + hd] + xr[hd];
                float zf = z0[8 + hd]  + z0[40 + hd] + z1[8 + hd]  + z1[40 + hd] + xr[8 + hd];
                float zg = z0[16 + hd] + z0[48 + hd] + z1[16 + hd] + z1[48 + hd] + xr[16 + hd];
                float zo = z0[24 + hd] + z0[56 + hd] + z1[24 + hd] + z1[56 + hd] + xr[24 + hd];
                float cn = sigm_(zf) * creg[hd] + sigm_(zi) * tanhf_(zg);
                float hn = sigm_(zo) * tanhf_(cn);
                creg[hd] = cn;
                hn8[hd] = hn;
            }
            unsigned hiP[4], loP[4];
#pragma unroll
            for (int q = 0; q < 4; ++q) {
                __nv_bfloat16 a0 = __float2bfloat16(hn8[2 * q]);
                __nv_bfloat16 a1 = __float2bfloat16(hn8[2 * q + 1]);
                __nv_bfloat16 l0 = __float2bfloat16(hn8[2 * q]     - __bfloat162float(a0));
                __nv_bfloat16 l1 = __float2bfloat16(hn8[2 * q + 1] - __bfloat162float(a1));
                hiP[q] = (unsigned)__bfloat16_as_ushort(a0) | ((unsigned)__bfloat16_as_ushort(a1) << 16);
                loP[q] = (unsigned)__bfloat16_as_ushort(l0) | ((unsigned)__bfloat16_as_ushort(l1) << 16);
            }
            const int nb = (t + 1) & 1;
            *(uint4*)&g_hbf[nb][0][eb * CH + hj] = make_uint4(hiP[0], hiP[1], hiP[2], hiP[3]);
            *(uint4*)&g_hbf[nb][1][eb * CH + hj] = make_uint4(loP[0], loP[1], loP[2], loP[3]);

            float* yp = y + (size_t)t * y_ts + (size_t)eb * y_bs + hj;
            *(float4*)(yp)     = make_float4(hn8[0], hn8[1], hn8[2], hn8[3]);
            *(float4*)(yp + 4) = make_float4(hn8[4], hn8[5], hn8[6], hn8[7]);

            if (t == CT - 1) {
#pragma unroll
                for (int hd = 0; hd < 8; ++hd) {
                    hOut[eb * CH + hj + hd] = hn8[hd];
                    cOut[eb * CH + hj + hd] = creg[hd];
                }
            }
        }
        // next grid_sync orders sZ/sX reuse and h visibility
    }
}

// ============================================================================
extern "C" void kernel_launch(void* const* d_in, const int* in_sizes, int n_in,
                              void* d_out, int out_size)
{
    const int*   x   = (const int*)  d_in[0];
    const float* h01 = (const float*)d_in[1];
    const float* c01 = (const float*)d_in[2];
    const float* h02 = (const float*)d_in[3];
    const float* c02 = (const float*)d_in[4];
    const float* emb = (const float*)d_in[5];
    const float* W1  = (const float*)d_in[6];
    const float* U1  = (const float*)d_in[7];
    const float* b1  = (const float*)d_in[8];
    const float* W2  = (const float*)d_in[9];
    const float* U2  = (const float*)d_in[10];
    const float* b2  = (const float*)d_in[11];

    float* out = (float*)d_out;
    float* h1o = out + (size_t)CB * CT * CH;
    float* c1o = h1o + CB * CH;
    float* h2o = c1o + CB * CH;
    float* c2o = h2o + CB * CH;

    float *xzp, *y1p;
    cudaGetSymbolAddress((void**)&xzp, g_xz);
    cudaGetSymbolAddress((void**)&y1p, g_y1);

    static int smem_set = 0;
    if (!smem_set) {
        cudaFuncSetAttribute(lstm_kernel,
                             cudaFuncAttributeMaxDynamicSharedMemorySize, SMW_BYTES);
        smem_set = 1;
    }

    dim3 gg(CG / 128, (CT * CB) / 128);   // (32, 64)

    // layer 1
    gemm_bias_kernel<true><<<gg, 256>>>(emb, x, W1, b1, xzp, CE);
    lstm_kernel<<<NCTA, LTHR, SMW_BYTES>>>(xzp, U1, y1p, CB * CH, CH,
                                           h01, c01, h1o, c1o);
    // layer 2
    gemm_bias_kernel<false><<<gg, 256>>>(y1p, nullptr, W2, b2, xzp, CH);
    lstm_kernel<<<NCTA, LTHR, SMW_BYTES>>>(xzp, U2, out, CH, CT * CH,
                                           h02, c02, h2o, c2o);
}

// round 14
// speedup vs baseline: 2.4917x; 1.0694x over previous
#include <cuda_runtime.h>
#include <cuda_bf16.h>
#include <cstdint>

typedef unsigned long long ull;

#define CB 64      // batch
#define CT 128     // time
#define CE 256     // embed
#define CH 1024    // hidden
#define CG 4096    // 4*H
#define NCTA 128   // persistent recurrence grid
#define LTHR 512   // lstm threads (16 warps)

// -------- scratch (device globals; no runtime allocation) --------
__device__ float g_xz[(size_t)CT * CB * CG];   // shared by layer1 & layer2
__device__ float g_y1[(size_t)CT * CB * CH];   // layer1 outputs [t][b][h]
__device__ __align__(16) unsigned short g_hbf[2][2][CB * CH]; // [buf][hi/lo][b*CH+k] bf16
__device__ unsigned g_bar;                     // monotonic grid-barrier counter

// -------- packed fp32 helpers (GEMM) --------
__device__ __forceinline__ ull ffma2(ull a, ull b, ull c) {
    ull d; asm("fma.rn.f32x2 %0,%1,%2,%3;" : "=l"(d) : "l"(a), "l"(b), "l"(c)); return d;
}
__device__ __forceinline__ ull pack2(float x, float y) {
    ull d; asm("mov.b64 %0,{%1,%2};" : "=l"(d) : "f"(x), "f"(y)); return d;
}
__device__ __forceinline__ float2 unpack2(ull v) {
    float2 r; asm("mov.b64 {%0,%1},%2;" : "=f"(r.x), "=f"(r.y) : "l"(v)); return r;
}

__device__ __forceinline__ float sigm_(float x)  { return __fdividef(1.f, 1.f + __expf(-x)); }
__device__ __forceinline__ float tanhf_(float x) { return __fdividef(2.f, 1.f + __expf(-2.f * x)) - 1.f; }

// Monotonic-counter grid barrier (no reset race; safe across graph replays).
__device__ __forceinline__ void grid_sync() {
    __threadfence();
    __syncthreads();
    if (threadIdx.x == 0) {
        unsigned old = atomicAdd(&g_bar, 1u);
        unsigned target = (old / NCTA + 1u) * NCTA;
        while (*((volatile unsigned*)&g_bar) < target) {}
        __threadfence();
    }
    __syncthreads();
}

// -------- warp MMA helpers (baseline PTX: works on sm_103 plain) --------
__device__ __forceinline__ void ldsm4(unsigned& r0, unsigned& r1, unsigned& r2, unsigned& r3,
                                      unsigned addr) {
    asm volatile("ldmatrix.sync.aligned.m8n8.x4.shared.b16 {%0,%1,%2,%3},[%4];"
                 : "=r"(r0), "=r"(r1), "=r"(r2), "=r"(r3) : "r"(addr));
}
#define MMA16816(d, a, b0, b1)                                              \
    asm volatile("mma.sync.aligned.m16n8k16.row.col.f32.bf16.bf16.f32 "     \
        "{%0,%1,%2,%3},{%4,%5,%6,%7},{%8,%9},{%0,%1,%2,%3};"                \
        : "+f"((d)[0]), "+f"((d)[1]), "+f"((d)[2]), "+f"((d)[3])            \
        : "r"((a)[0]), "r"((a)[1]), "r"((a)[2]), "r"((a)[3]),               \
          "r"(b0), "r"(b1))

// ============================================================================
// GEMM: C[M, 4096] = A[M,K] @ W[K,4096] + bias, optional row gather (emb).
// (unchanged — proven)
// ============================================================================
template <bool GATHER>
__global__ __launch_bounds__(256) void gemm_bias_kernel(
    const float* __restrict__ A, const int* __restrict__ xidx,
    const float* __restrict__ W, const float* __restrict__ bias,
    float* __restrict__ C, int K)
{
    __shared__ float As[2][16][132];
    __shared__ float Ws[2][16][128];

    const int tid  = threadIdx.x;
    const int n0   = blockIdx.x * 128;
    const int m0   = blockIdx.y * 128;
    const int trow = tid >> 4;
    const int tcol = tid & 15;

    const int sr  = tid >> 2;
    const int skq = (tid & 3) * 4;
    const float* arow0;
    const float* arow1;
    {
        int ma = m0 + sr, mb = m0 + sr + 64;
        if (GATHER) {
            int ia = xidx[(ma % CB) * CT + (ma / CB)];
            int ib = xidx[(mb % CB) * CT + (mb / CB)];
            arow0 = A + (size_t)ia * K;
            arow1 = A + (size_t)ib * K;
        } else {
            arow0 = A + (size_t)ma * K;
            arow1 = A + (size_t)mb * K;
        }
    }
    const int wk  = tid >> 5;
    const int wc4 = (tid & 31) * 4;

    ull acc[8][4];
#pragma unroll
    for (int r = 0; r < 8; ++r)
#pragma unroll
        for (int j = 0; j < 4; ++j) acc[r][j] = pack2(0.f, 0.f);

    const int nk = K / 16;
    float4 pa0, pa1, pw0, pw1;

    pa0 = *(const float4*)(arow0 + skq);
    pa1 = *(const float4*)(arow1 + skq);
    pw0 = *(const float4*)(W + (size_t)wk * CG + n0 + wc4);
    pw1 = *(const float4*)(W + (size_t)(wk + 8) * CG + n0 + wc4);

    As[0][skq + 0][sr] = pa0.x; As[0][skq + 1][sr] = pa0.y;
    As[0][skq + 2][sr] = pa0.z; As[0][skq + 3][sr] = pa0.w;
    As[0][skq + 0][sr + 64] = pa1.x; As[0][skq + 1][sr + 64] = pa1.y;
    As[0][skq + 2][sr + 64] = pa1.z; As[0][skq + 3][sr + 64] = pa1.w;
    *(float4*)&Ws[0][wk][wc4]     = pw0;
    *(float4*)&Ws[0][wk + 8][wc4] = pw1;
    __syncthreads();

    int p = 0;
    for (int kt = 0; kt < nk; ++kt) {
        const int k0n = (kt + 1) * 16;
        if (kt + 1 < nk) {
            pa0 = *(const float4*)(arow0 + k0n + skq);
            pa1 = *(const float4*)(arow1 + k0n + skq);
            pw0 = *(const float4*)(W + (size_t)(k0n + wk) * CG + n0 + wc4);
            pw1 = *(const float4*)(W + (size_t)(k0n + wk + 8) * CG + n0 + wc4);
        }
#pragma unroll
        for (int kk = 0; kk < 16; ++kk) {
            float4 a0 = *(const float4*)&As[p][kk][trow * 8];
            float4 a1 = *(const float4*)&As[p][kk][trow * 8 + 4];
            ulonglong2 b01 = *(const ulonglong2*)&Ws[p][kk][tcol * 8];
            ulonglong2 b23 = *(const ulonglong2*)&Ws[p][kk][tcol * 8 + 4];
            float av[8] = {a0.x, a0.y, a0.z, a0.w, a1.x, a1.y, a1.z, a1.w};
            ull bv[4] = {b01.x, b01.y, b23.x, b23.y};
#pragma unroll
            for (int r = 0; r < 8; ++r) {
                ull ad = pack2(av[r], av[r]);
#pragma unroll
                for (int j = 0; j < 4; ++j) acc[r][j] = ffma2(ad, bv[j], acc[r][j]);
            }
        }
        if (kt + 1 < nk) {
            int q = p ^ 1;
            As[q][skq + 0][sr] = pa0.x; As[q][skq + 1][sr] = pa0.y;
            As[q][skq + 2][sr] = pa0.z; As[q][skq + 3][sr] = pa0.w;
            As[q][skq + 0][sr + 64] = pa1.x; As[q][skq + 1][sr + 64] = pa1.y;
            As[q][skq + 2][sr + 64] = pa1.z; As[q][skq + 3][sr + 64] = pa1.w;
            *(float4*)&Ws[q][wk][wc4]     = pw0;
            *(float4*)&Ws[q][wk + 8][wc4] = pw1;
        }
        __syncthreads();
        p ^= 1;
    }

    float bv[8];
#pragma unroll
    for (int j = 0; j < 8; ++j) bv[j] = bias[n0 + tcol * 8 + j];
#pragma unroll
    for (int r = 0; r < 8; ++r) {
        float* crow = C + (size_t)(m0 + trow * 8 + r) * CG + n0 + tcol * 8;
        float2 t0 = unpack2(acc[r][0]), t1 = unpack2(acc[r][1]);
        float2 t2 = unpack2(acc[r][2]), t3 = unpack2(acc[r][3]);
        float4 v0 = {t0.x + bv[0], t0.y + bv[1], t1.x + bv[2], t1.y + bv[3]};
        float4 v1 = {t2.x + bv[4], t2.y + bv[5], t3.x + bv[6], t3.y + bv[7]};
        *(float4*)(crow)     = v0;
        *(float4*)(crow + 4) = v1;
    }
}

// ============================================================================
// Persistent LSTM layer on warp-level MMA (mma.sync bf16).
// Round 14: 3-buffer ring (1 barrier/chunk), epilogue on all 512 threads.
//
// Per CTA: z[64 b][32 c] via D[128 m][64 n]:
//   A rows  0-63 = h_hi bf16, 64-127 = h_lo (residual);
//   B cols  0-31 = U_hi,      32-63  = U_lo.
//   z[b][c] = D[b][c] + D[b][c+32] + D[b+64][c] + D[b+64][c+32]
// ============================================================================

// smem layout (bytes):
#define SMW_U 0                         // U hi/lo [64 n][1024 k] bf16: 131072
#define SMW_A 131072                    // 3 x A chunk [128][64] bf16: 49152
#define SMW_Z (131072 + 49152)          // D partials [128][72] f32: 36864
#define SMW_X (SMW_Z + 36864)           // xz stage [64][36] f32: 9216
#define SMW_BYTES (SMW_X + 9216)        // 226304

__device__ __forceinline__ void load_chunkW(unsigned dstBase, int hbuf, int kb, int tid) {
#pragma unroll
    for (int j = 0; j < 2; ++j) {
        int idx = tid + j * LTHR;        // 0..1023
        int m   = idx >> 3;              // 0..127 (0-63 hi, 64-127 lo)
        int g8  = idx & 7;               // 16B granule within 128B row
        int part = m >> 6, b = m & 63;
        const unsigned short* src = &g_hbf[hbuf][part][b * CH + kb + g8 * 8];
        unsigned dst = dstBase + (unsigned)(m * 128 + ((g8 * 16) ^ ((m & 7) << 4)));
        asm volatile("cp.async.cg.shared.global [%0],[%1],16;" :: "r"(dst), "l"(src));
    }
    asm volatile("cp.async.commit_group;");
}

__global__ __launch_bounds__(LTHR, 1) void lstm_kernel(
    const float* __restrict__ xz, const float* __restrict__ U,
    float* __restrict__ y, int y_ts, int y_bs,
    const float* __restrict__ h0, const float* __restrict__ c0,
    float* __restrict__ hOut, float* __restrict__ cOut)
{
    extern __shared__ char smc[];
    const unsigned sb = (unsigned)__cvta_generic_to_shared(smc);
    float* sZ = (float*)(smc + SMW_Z);
    float* sX = (float*)(smc + SMW_X);

    const int tid  = threadIdx.x;
    const int cta  = blockIdx.x;
    const int hj   = cta * 8;
    const int lane = tid & 31, w = tid >> 5;
    const int mp = w & 3, nh = (w >> 2) & 1, kh = w >> 3;

    // ---- init h-state bf16 hi/lo (all CTAs cooperate) ----
    for (int e = cta * LTHR + tid; e < CB * CH; e += NCTA * LTHR) {
        float v = h0[e];
        __nv_bfloat16 hi = __float2bfloat16(v);
        __nv_bfloat16 lo = __float2bfloat16(v - __bfloat162float(hi));
        g_hbf[0][0][e] = __bfloat16_as_ushort(hi);
        g_hbf[0][1][e] = __bfloat16_as_ushort(lo);
    }

    // ---- U slice -> smem [64 n][1024 k] bf16, rows 0-31 hi, 32-63 lo ----
    for (int idx = tid; idx < 64 * CH; idx += LTHR) {
        int n = idx & 63, k = idx >> 6;
        int c = n & 31;
        int gc = (c >> 3) * CH + hj + (c & 7);
        float v = U[(size_t)k * CG + gc];
        __nv_bfloat16 hi = __float2bfloat16(v);
        __nv_bfloat16 val = (n < 32) ? hi : __float2bfloat16(v - __bfloat162float(hi));
        unsigned byt = (unsigned)(n * 2048 + ((k * 2) ^ ((n & 7) << 4)));
        *(__nv_bfloat16*)(smc + SMW_U + byt) = val;
    }

    // ---- c state: 1 float per thread (b = tid>>3, hd = tid&7) ----
    const int gb = tid >> 3, ghd = tid & 7;
    float creg = c0[gb * CH + hj + ghd];
    __syncthreads();

    // ---- per-lane ldmatrix address components ----
    const int rowA = 32 * mp + (lane & 7) + 8 * ((lane >> 3) & 1);
    const unsigned aB1 = sb + SMW_A + (unsigned)(rowA * 128);
    const unsigned aB2 = aB1 + 16 * 128;
    const unsigned mx  = (unsigned)((rowA & 7) << 4);
    const unsigned kh16A = (unsigned)(((lane >> 4) & 1) * 16);

    const int nB = 32 * nh + ((lane >> 4) & 1) * 8 + (lane & 7);
    const unsigned bB1 = sb + SMW_U + (unsigned)(nB * 2048);
    const unsigned bB2 = bB1 + 16 * 2048;
    const unsigned nx  = (unsigned)((nB & 7) << 4);
    const unsigned kplusB = (unsigned)(((lane >> 3) & 1) * 16);

    // xz cp.async decode
    const int xb = tid >> 3, xseg = tid & 7;
    const int xgate = xseg >> 1, xhalf = xseg & 1;

    for (int t = 0; t < CT; ++t) {
        grid_sync();   // all CTAs published h[t]; also orders sX/sZ reuse
        const int hbuf = t & 1;

        float acc[32];
#pragma unroll
        for (int q = 0; q < 32; ++q) acc[q] = 0.f;

        // G_xz: xz stage
        {
            const float* src = xz + (size_t)t * CB * CG + (size_t)xb * CG
                               + xgate * CH + hj + xhalf * 4;
            unsigned dst = sb + SMW_X + (unsigned)((xb * 36 + xgate * 8 + xhalf * 4) * 4);
            asm volatile("cp.async.cg.shared.global [%0],[%1],16;" :: "r"(dst), "l"(src));
            asm volatile("cp.async.commit_group;");
        }
        // G0, G1: chunks 0, 1 into ring buffers 0, 1
        load_chunkW(sb + SMW_A,         hbuf, 0,  tid);
        load_chunkW(sb + SMW_A + 16384, hbuf, 64, tid);

        int rb2 = 2;   // ring index of chunk ch+2
        for (int ch = 0; ch < 16; ++ch) {
            if (ch < 15) asm volatile("cp.async.wait_group 1;" ::: "memory");
            else         asm volatile("cp.async.wait_group 0;" ::: "memory");
            __syncthreads();   // chunk ch ready; all warps done with chunk ch-1

            // refill the buffer chunk ch-1 used (safe: barrier above)
            if (ch + 2 < 16) {
                load_chunkW(sb + SMW_A + (unsigned)(rb2 * 16384), hbuf,
                            (ch + 2) * 64, tid);
            }
            const unsigned abb = (unsigned)(((ch * 43) >> 7) ? 0u : 0u) ; // placeholder no-op
            const unsigned abase = (unsigned)((ch % 3) * 16384);
#pragma unroll
            for (int ks = 0; ks < 2; ++ks) {
                const int kl = kh * 2 + ks;                  // kstep within chunk
                const unsigned kofsA = (unsigned)(kl * 32 + kh16A) ^ mx;
                unsigned a0[4], a1[4], b0[4], b1[4];
                ldsm4(a0[0], a0[1], a0[2], a0[3], aB1 + abase + kofsA);
                ldsm4(a1[0], a1[1], a1[2], a1[3], aB2 + abase + kofsA);
                const unsigned kB = (unsigned)(ch * 128 + kl * 32 + kplusB) ^ nx;
                ldsm4(b0[0], b0[1], b0[2], b0[3], bB1 + kB);
                ldsm4(b1[0], b1[1], b1[2], b1[3], bB2 + kB);
                MMA16816(acc + 0,  a0, b0[0], b0[1]);
                MMA16816(acc + 4,  a0, b0[2], b0[3]);
                MMA16816(acc + 8,  a0, b1[0], b1[1]);
                MMA16816(acc + 12, a0, b1[2], b1[3]);
                MMA16816(acc + 16, a1, b0[0], b0[1]);
                MMA16816(acc + 20, a1, b0[2], b0[3]);
                MMA16816(acc + 24, a1, b1[0], b1[1]);
                MMA16816(acc + 28, a1, b1[2], b1[3]);
            }
            rb2 = (rb2 == 2) ? 0 : rb2 + 1;
            (void)abb;
        }

        // ---- 2-phase k-half reduction into sZ[128][72] ----
        const int g   = lane >> 2;
        const int tg2 = (lane & 3) * 2;
        if (kh == 0) {
#pragma unroll
            for (int mt = 0; mt < 2; ++mt)
#pragma unroll
                for (int nt = 0; nt < 4; ++nt) {
                    const float* a = acc + (mt * 4 + nt) * 4;
                    float* p = sZ + (32 * mp + mt * 16 + g) * 72 + 32 * nh + nt * 8 + tg2;
                    *(float2*)p            = make_float2(a[0], a[1]);
                    *(float2*)(p + 8 * 72) = make_float2(a[2], a[3]);
                }
        }
        __syncthreads();
        if (kh == 1) {
#pragma unroll
            for (int mt = 0; mt < 2; ++mt)
#pragma unroll
                for (int nt = 0; nt < 4; ++nt) {
                    const float* a = acc + (mt * 4 + nt) * 4;
                    float* p = sZ + (32 * mp + mt * 16 + g) * 72 + 32 * nh + nt * 8 + tg2;
                    float2 v0 = *(float2*)p;
                    float2 v1 = *(float2*)(p + 8 * 72);
                    *(float2*)p            = make_float2(v0.x + a[0], v0.y + a[1]);
                    *(float2*)(p + 8 * 72) = make_float2(v1.x + a[2], v1.y + a[3]);
                }
        }
        __syncthreads();

        // ---- gates: all 512 threads, one (b, hd) each ----
        {
            const float* z0 = sZ + gb * 72;          // h_hi rows
            const float* z1 = sZ + (gb + 64) * 72;   // h_lo rows
            const float* xr = sX + gb * 36;
            float zi = z0[ghd]      + z0[32 + ghd] + z1[ghd]      + z1[32 + ghd] + xr[ghd];
            float zf = z0[8 + ghd]  + z0[40 + ghd] + z1[8 + ghd]  + z1[40 + ghd] + xr[8 + ghd];
            float zg = z0[16 + ghd] + z0[48 + ghd] + z1[16 + ghd] + z1[48 + ghd] + xr[16 + ghd];
            float zo = z0[24 + ghd] + z0[56 + ghd] + z1[24 + ghd] + z1[56 + ghd] + xr[24 + ghd];
            float cn = sigm_(zf) * creg + sigm_(zi) * tanhf_(zg);
            float hn = sigm_(zo) * tanhf_(cn);
            creg = cn;

            __nv_bfloat16 hi = __float2bfloat16(hn);
            __nv_bfloat16 lo = __float2bfloat16(hn - __bfloat162float(hi));
            const int nb = (t + 1) & 1;
            const int off = gb * CH + hj + ghd;
            g_hbf[nb][0][off] = __bfloat16_as_ushort(hi);
            g_hbf[nb][1][off] = __bfloat16_as_ushort(lo);

            y[(size_t)t * y_ts + (size_t)gb * y_bs + hj + ghd] = hn;
            if (t == CT - 1) {
                hOut[off] = hn;
                cOut[off] = cn;
            }
        }
        // next grid_sync orders sZ/sX reuse and h visibility
    }
}

// ============================================================================
extern "C" void kernel_launch(void* const* d_in, const int* in_sizes, int n_in,
                              void* d_out, int out_size)
{
    const int*   x   = (const int*)  d_in[0];
    const float* h01 = (const float*)d_in[1];
    const float* c01 = (const float*)d_in[2];
    const float* h02 = (const float*)d_in[3];
    const float* c02 = (const float*)d_in[4];
    const float* emb = (const float*)d_in[5];
    const float* W1  = (const float*)d_in[6];
    const float* U1  = (const float*)d_in[7];
    const float* b1  = (const float*)d_in[8];
    const float* W2  = (const float*)d_in[9];
    const float* U2  = (const float*)d_in[10];
    const float* b2  = (const float*)d_in[11];

    float* out = (float*)d_out;
    float* h1o = out + (size_t)CB * CT * CH;
    float* c1o = h1o + CB * CH;
    float* h2o = c1o + CB * CH;
    float* c2o = h2o + CB * CH;

    float *xzp, *y1p;
    cudaGetSymbolAddress((void**)&xzp, g_xz);
    cudaGetSymbolAddress((void**)&y1p, g_y1);

    static int smem_set = 0;
    if (!smem_set) {
        cudaFuncSetAttribute(lstm_kernel,
                             cudaFuncAttributeMaxDynamicSharedMemorySize, SMW_BYTES);
        smem_set = 1;
    }

    dim3 gg(CG / 128, (CT * CB) / 128);   // (32, 64)

    // layer 1
    gemm_bias_kernel<true><<<gg, 256>>>(emb, x, W1, b1, xzp, CE);
    lstm_kernel<<<NCTA, LTHR, SMW_BYTES>>>(xzp, U1, y1p, CB * CH, CH,
                                           h01, c01, h1o, c1o);
    // layer 2
    gemm_bias_kernel<false><<<gg, 256>>>(y1p, nullptr, W2, b2, xzp, CH);
    lstm_kernel<<<NCTA, LTHR, SMW_BYTES>>>(xzp, U2, out, CH, CT * CH,
                                           h02, c02, h2o, c2o);
}

// round 15
// speedup vs baseline: 3.7624x; 1.5100x over previous
#include <cuda_runtime.h>
#include <cuda_bf16.h>
#include <cstdint>

typedef unsigned long long ull;

#define CB 64      // batch
#define CT 128     // time
#define CE 256     // embed
#define CH 1024    // hidden
#define CG 4096    // 4*H
#define NCTA 128   // persistent recurrence grid
#define LTHR 512   // lstm threads (16 warps)

// -------- scratch (device globals; no runtime allocation) --------
__device__ float g_xz[(size_t)CT * CB * CG];                      // 134 MB
__device__ __align__(16) unsigned short g_hbf[2][2][CB * CH];     // h state bf16 hi/lo
__device__ __align__(16) unsigned short g_wbf[2][(size_t)CH * CG];        // W bf16 hi/lo
__device__ __align__(16) unsigned short g_abf[2][(size_t)CT * CB * CH];   // A bf16 hi/lo
__device__ unsigned g_bar;

__device__ __forceinline__ float sigm_(float x)  { return __fdividef(1.f, 1.f + __expf(-x)); }
__device__ __forceinline__ float tanhf_(float x) { return __fdividef(2.f, 1.f + __expf(-2.f * x)) - 1.f; }

// Monotonic-counter grid barrier (no reset race; safe across graph replays).
__device__ __forceinline__ void grid_sync() {
    __threadfence();
    __syncthreads();
    if (threadIdx.x == 0) {
        unsigned old = atomicAdd(&g_bar, 1u);
        unsigned target = (old / NCTA + 1u) * NCTA;
        while (*((volatile unsigned*)&g_bar) < target) {}
        __threadfence();
    }
    __syncthreads();
}

// -------- warp MMA helpers (baseline PTX: works on sm_103 plain) --------
__device__ __forceinline__ void ldsm4(unsigned& r0, unsigned& r1, unsigned& r2, unsigned& r3,
                                      unsigned addr) {
    asm volatile("ldmatrix.sync.aligned.m8n8.x4.shared.b16 {%0,%1,%2,%3},[%4];"
                 : "=r"(r0), "=r"(r1), "=r"(r2), "=r"(r3) : "r"(addr));
}
__device__ __forceinline__ void ldsm4t(unsigned& r0, unsigned& r1, unsigned& r2, unsigned& r3,
                                       unsigned addr) {
    asm volatile("ldmatrix.sync.aligned.m8n8.x4.trans.shared.b16 {%0,%1,%2,%3},[%4];"
                 : "=r"(r0), "=r"(r1), "=r"(r2), "=r"(r3) : "r"(addr));
}
#define MMA16816(d, a, b0, b1)                                              \
    asm volatile("mma.sync.aligned.m16n8k16.row.col.f32.bf16.bf16.f32 "     \
        "{%0,%1,%2,%3},{%4,%5,%6,%7},{%8,%9},{%0,%1,%2,%3};"                \
        : "+f"((d)[0]), "+f"((d)[1]), "+f"((d)[2]), "+f"((d)[3])            \
        : "r"((a)[0]), "r"((a)[1]), "r"((a)[2]), "r"((a)[3]),               \
          "r"(b0), "r"(b1))

// ============================================================================
// Conversion kernels
// ============================================================================
__global__ __launch_bounds__(256) void conv_w_kernel(const float* __restrict__ W, int total) {
    int i = blockIdx.x * 256 + threadIdx.x;
    if (i < total) {
        float v = W[i];
        __nv_bfloat16 hi = __float2bfloat16(v);
        __nv_bfloat16 lo = __float2bfloat16(v - __bfloat162float(hi));
        g_wbf[0][i] = __bfloat16_as_ushort(hi);
        g_wbf[1][i] = __bfloat16_as_ushort(lo);
    }
}

// Gathered embedding rows -> bf16 hi/lo, row m = t*64+b, K=256
__global__ __launch_bounds__(256) void conv_emb_kernel(
    const float* __restrict__ emb, const int* __restrict__ x) {
    int m = blockIdx.x, k = threadIdx.x;
    int b = m & 63, t = m >> 6;
    int ia = x[b * CT + t];
    float v = emb[(size_t)ia * CE + k];
    __nv_bfloat16 hi = __float2bfloat16(v);
    __nv_bfloat16 lo = __float2bfloat16(v - __bfloat162float(hi));
    g_abf[0][(size_t)m * CE + k] = __bfloat16_as_ushort(hi);
    g_abf[1][(size_t)m * CE + k] = __bfloat16_as_ushort(lo);
}

// ============================================================================
// Split-bf16 tensor GEMM: C[8192][4096] = (Ah+Al)@(Wh+Wl) + bias
// 3 passes: Ah@Wh + Ah@Wl + Al@Wh  (Al@Wl ~ 2^-18, dropped)
// BM=128, BN=128, BK=64, 256 thr / 8 warps (4 m-quads x 2 n-halves),
// 3-buffer ring (32 KB per buffer: A 16K + B 16K), 1 barrier per segment.
// ============================================================================
#define GSM_BYTES (3 * 32768)

__device__ __forceinline__ void g_load_seg(
    unsigned bufBase, const unsigned short* __restrict__ A,
    const unsigned short* __restrict__ W,
    int K, int m0, int n0, int kc, int tid)
{
#pragma unroll
    for (int j = 0; j < 4; ++j) {         // A tile [128 m][64 k]
        int idx = tid + j * 256;          // 0..1023
        int m = idx >> 3, g = idx & 7;
        const unsigned short* src = A + (size_t)(m0 + m) * K + kc * 64 + g * 8;
        unsigned d = bufBase + (unsigned)(m * 128 + ((g * 16) ^ ((m & 7) << 4)));
        asm volatile("cp.async.cg.shared.global [%0],[%1],16;" :: "r"(d), "l"(src));
    }
#pragma unroll
    for (int j = 0; j < 4; ++j) {         // B tile [64 k][128 n]
        int idx = tid + j * 256;
        int k = idx >> 4, g = idx & 15;
        const unsigned short* src = W + (size_t)(kc * 64 + k) * CG + n0 + g * 8;
        unsigned d = bufBase + 16384u + (unsigned)(k * 256 + ((g * 16) ^ ((k & 7) << 4)));
        asm volatile("cp.async.cg.shared.global [%0],[%1],16;" :: "r"(d), "l"(src));
    }
    asm volatile("cp.async.commit_group;");
}

__global__ __launch_bounds__(256, 2) void mma_gemm_kernel(
    const float* __restrict__ bias, float* __restrict__ C, int K)
{
    extern __shared__ char gsm[];
    const unsigned sb = (unsigned)__cvta_generic_to_shared(gsm);

    const int tid  = threadIdx.x;
    const int lane = tid & 31, w = tid >> 5;
    const int mq = w & 3, nh = w >> 2;
    const int n0g = blockIdx.x * 128;
    const int m0g = blockIdx.y * 128;

    const int kseg = K / 64;
    const int nseg = 3 * kseg;

    // per-lane ldmatrix components
    const int rA = mq * 32 + (lane & 15);
    const unsigned aBase = (unsigned)(rA * 128);
    const unsigned aSw   = (unsigned)((rA & 7) << 4);
    const unsigned aKh   = (unsigned)(((lane >> 4) & 1) * 16);

    const int kB = lane & 15;
    const unsigned bRow = (unsigned)(kB * 256);
    const unsigned bSw  = (unsigned)((kB & 7) << 4);
    const unsigned bNh  = (unsigned)(nh * 128 + ((lane >> 4) & 1) * 16);

    float acc[64];
#pragma unroll
    for (int q = 0; q < 64; ++q) acc[q] = 0.f;

    // seg s: pass p = s / kseg, kc = s % kseg
    //   pass 0: Ah@Wh ; pass 1: Ah@Wl ; pass 2: Al@Wh
    const unsigned short* Asrc[3] = { g_abf[0], g_abf[0], g_abf[1] };
    const unsigned short* Wsrc[3] = { g_wbf[0], g_wbf[1], g_wbf[0] };

    g_load_seg(sb,          Asrc[0], Wsrc[0], K, m0g, n0g, 0, tid);
    {
        int p1 = 1 / kseg, kc1 = 1 % kseg;   // seg 1 (kseg>=4 so p1=0, kc1=1)
        g_load_seg(sb + 32768, Asrc[p1], Wsrc[p1], K, m0g, n0g, kc1, tid);
    }

    for (int s = 0; s < nseg; ++s) {
        if (s + 1 < nseg) asm volatile("cp.async.wait_group 1;" ::: "memory");
        else              asm volatile("cp.async.wait_group 0;" ::: "memory");
        __syncthreads();   // seg s ready; all warps done with seg s-1

        if (s + 2 < nseg) {
            int s2 = s + 2;
            g_load_seg(sb + (unsigned)((s2 % 3) * 32768),
                       Asrc[s2 / kseg], Wsrc[s2 / kseg], K, m0g, n0g, s2 % kseg, tid);
        }

        const unsigned sa  = sb + (unsigned)((s % 3) * 32768);
        const unsigned sbb = sa + 16384u;
#pragma unroll
        for (int ks = 0; ks < 4; ++ks) {
            unsigned a0[4], a1[4];
            const unsigned ka = ((unsigned)(ks * 32) + aKh) ^ aSw;
            ldsm4(a0[0], a0[1], a0[2], a0[3], sa + aBase + ka);
            ldsm4(a1[0], a1[1], a1[2], a1[3], sa + aBase + 16 * 128 + ka);
#pragma unroll
            for (int q = 0; q < 4; ++q) {
                unsigned b[4];
                const unsigned nb = (bNh + (unsigned)(q * 32)) ^ bSw;
                ldsm4t(b[0], b[1], b[2], b[3], sbb + bRow + (unsigned)(ks * 4096) + nb);
                MMA16816(acc + ((q * 2 + 0)) * 4,      a0, b[0], b[1]);
                MMA16816(acc + ((q * 2 + 1)) * 4,      a0, b[2], b[3]);
                MMA16816(acc + (8 + q * 2 + 0) * 4,    a1, b[0], b[1]);
                MMA16816(acc + (8 + q * 2 + 1) * 4,    a1, b[2], b[3]);
            }
        }
    }

    // epilogue: bias + store fp32
#pragma unroll
    for (int nt = 0; nt < 8; ++nt) {
        int col = n0g + nh * 64 + nt * 8 + (lane & 3) * 2;
        float b0 = bias[col], b1 = bias[col + 1];
#pragma unroll
        for (int mt = 0; mt < 2; ++mt) {
            const float* a = acc + (mt * 8 + nt) * 4;
            int row = m0g + mq * 32 + mt * 16 + (lane >> 2);
            *(float2*)&C[(size_t)row * CG + col]       = make_float2(a[0] + b0, a[1] + b1);
            *(float2*)&C[(size_t)(row + 8) * CG + col] = make_float2(a[2] + b0, a[3] + b1);
        }
    }
}

// ============================================================================
// Persistent LSTM layer on warp-level MMA (unchanged pipeline from R14).
// New: layer-1 mode writes y as bf16 hi/lo into g_abf (feeds proj2 directly).
// ============================================================================
#define SMW_U 0
#define SMW_A 131072
#define SMW_Z (131072 + 49152)
#define SMW_X (SMW_Z + 36864)
#define SMW_BYTES (SMW_X + 9216)        // 226304

__device__ __forceinline__ void load_chunkW(unsigned dstBase, int hbuf, int kb, int tid) {
#pragma unroll
    for (int j = 0; j < 2; ++j) {
        int idx = tid + j * LTHR;
        int m   = idx >> 3;
        int g8  = idx & 7;
        int part = m >> 6, b = m & 63;
        const unsigned short* src = &g_hbf[hbuf][part][b * CH + kb + g8 * 8];
        unsigned dst = dstBase + (unsigned)(m * 128 + ((g8 * 16) ^ ((m & 7) << 4)));
        asm volatile("cp.async.cg.shared.global [%0],[%1],16;" :: "r"(dst), "l"(src));
    }
    asm volatile("cp.async.commit_group;");
}

__global__ __launch_bounds__(LTHR, 1) void lstm_kernel(
    const float* __restrict__ xz, const float* __restrict__ U,
    float* __restrict__ y, int y_ts, int y_bs,
    unsigned short* __restrict__ ybh, unsigned short* __restrict__ ybl,
    const float* __restrict__ h0, const float* __restrict__ c0,
    float* __restrict__ hOut, float* __restrict__ cOut)
{
    extern __shared__ char smc[];
    const unsigned sb = (unsigned)__cvta_generic_to_shared(smc);
    float* sZ = (float*)(smc + SMW_Z);
    float* sX = (float*)(smc + SMW_X);

    const int tid  = threadIdx.x;
    const int cta  = blockIdx.x;
    const int hj   = cta * 8;
    const int lane = tid & 31, w = tid >> 5;
    const int mp = w & 3, nh = (w >> 2) & 1, kh = w >> 3;

    for (int e = cta * LTHR + tid; e < CB * CH; e += NCTA * LTHR) {
        float v = h0[e];
        __nv_bfloat16 hi = __float2bfloat16(v);
        __nv_bfloat16 lo = __float2bfloat16(v - __bfloat162float(hi));
        g_hbf[0][0][e] = __bfloat16_as_ushort(hi);
        g_hbf[0][1][e] = __bfloat16_as_ushort(lo);
    }

    for (int idx = tid; idx < 64 * CH; idx += LTHR) {
        int n = idx & 63, k = idx >> 6;
        int c = n & 31;
        int gc = (c >> 3) * CH + hj + (c & 7);
        float v = U[(size_t)k * CG + gc];
        __nv_bfloat16 hi = __float2bfloat16(v);
        __nv_bfloat16 val = (n < 32) ? hi : __float2bfloat16(v - __bfloat162float(hi));
        unsigned byt = (unsigned)(n * 2048 + ((k * 2) ^ ((n & 7) << 4)));
        *(__nv_bfloat16*)(smc + SMW_U + byt) = val;
    }

    const int gb = tid >> 3, ghd = tid & 7;
    float creg = c0[gb * CH + hj + ghd];
    __syncthreads();

    const int rowA = 32 * mp + (lane & 7) + 8 * ((lane >> 3) & 1);
    const unsigned aB1 = sb + SMW_A + (unsigned)(rowA * 128);
    const unsigned aB2 = aB1 + 16 * 128;
    const unsigned mx  = (unsigned)((rowA & 7) << 4);
    const unsigned kh16A = (unsigned)(((lane >> 4) & 1) * 16);

    const int nB = 32 * nh + ((lane >> 4) & 1) * 8 + (lane & 7);
    const unsigned bB1 = sb + SMW_U + (unsigned)(nB * 2048);
    const unsigned bB2 = bB1 + 16 * 2048;
    const unsigned nx  = (unsigned)((nB & 7) << 4);
    const unsigned kplusB = (unsigned)(((lane >> 3) & 1) * 16);

    const int xb = tid >> 3, xseg = tid & 7;
    const int xgate = xseg >> 1, xhalf = xseg & 1;

    for (int t = 0; t < CT; ++t) {
        grid_sync();
        const int hbuf = t & 1;

        float acc[32];
#pragma unroll
        for (int q = 0; q < 32; ++q) acc[q] = 0.f;

        {
            const float* src = xz + (size_t)t * CB * CG + (size_t)xb * CG
                               + xgate * CH + hj + xhalf * 4;
            unsigned dst = sb + SMW_X + (unsigned)((xb * 36 + xgate * 8 + xhalf * 4) * 4);
            asm volatile("cp.async.cg.shared.global [%0],[%1],16;" :: "r"(dst), "l"(src));
            asm volatile("cp.async.commit_group;");
        }
        load_chunkW(sb + SMW_A,         hbuf, 0,  tid);
        load_chunkW(sb + SMW_A + 16384, hbuf, 64, tid);

        int rb2 = 2;
        for (int ch = 0; ch < 16; ++ch) {
            if (ch < 15) asm volatile("cp.async.wait_group 1;" ::: "memory");
            else         asm volatile("cp.async.wait_group 0;" ::: "memory");
            __syncthreads();

            if (ch + 2 < 16) {
                load_chunkW(sb + SMW_A + (unsigned)(rb2 * 16384), hbuf,
                            (ch + 2) * 64, tid);
            }
            const unsigned abase = (unsigned)((ch % 3) * 16384);
#pragma unroll
            for (int ks = 0; ks < 2; ++ks) {
                const int kl = kh * 2 + ks;
                const unsigned kofsA = (unsigned)(kl * 32 + kh16A) ^ mx;
                unsigned a0[4], a1[4], b0[4], b1[4];
                ldsm4(a0[0], a0[1], a0[2], a0[3], aB1 + abase + kofsA);
                ldsm4(a1[0], a1[1], a1[2], a1[3], aB2 + abase + kofsA);
                const unsigned kB = (unsigned)(ch * 128 + kl * 32 + kplusB) ^ nx;
                ldsm4(b0[0], b0[1], b0[2], b0[3], bB1 + kB);
                ldsm4(b1[0], b1[1], b1[2], b1[3], bB2 + kB);
                MMA16816(acc + 0,  a0, b0[0], b0[1]);
                MMA16816(acc + 4,  a0, b0[2], b0[3]);
                MMA16816(acc + 8,  a0, b1[0], b1[1]);
                MMA16816(acc + 12, a0, b1[2], b1[3]);
                MMA16816(acc + 16, a1, b0[0], b0[1]);
                MMA16816(acc + 20, a1, b0[2], b0[3]);
                MMA16816(acc + 24, a1, b1[0], b1[1]);
                MMA16816(acc + 28, a1, b1[2], b1[3]);
            }
            rb2 = (rb2 == 2) ? 0 : rb2 + 1;
        }

        const int g   = lane >> 2;
        const int tg2 = (lane & 3) * 2;
        if (kh == 0) {
#pragma unroll
            for (int mt = 0; mt < 2; ++mt)
#pragma unroll
                for (int nt = 0; nt < 4; ++nt) {
                    const float* a = acc + (mt * 4 + nt) * 4;
                    float* p = sZ + (32 * mp + mt * 16 + g) * 72 + 32 * nh + nt * 8 + tg2;
                    *(float2*)p            = make_float2(a[0], a[1]);
                    *(float2*)(p + 8 * 72) = make_float2(a[2], a[3]);
                }
        }
        __syncthreads();
        if (kh == 1) {
#pragma unroll
            for (int mt = 0; mt < 2; ++mt)
#pragma unroll
                for (int nt = 0; nt < 4; ++nt) {
                    const float* a = acc + (mt * 4 + nt) * 4;
                    float* p = sZ + (32 * mp + mt * 16 + g) * 72 + 32 * nh + nt * 8 + tg2;
                    float2 v0 = *(float2*)p;
                    float2 v1 = *(float2*)(p + 8 * 72);
                    *(float2*)p            = make_float2(v0.x + a[0], v0.y + a[1]);
                    *(float2*)(p + 8 * 72) = make_float2(v1.x + a[2], v1.y + a[3]);
                }
        }
        __syncthreads();

        {
            const float* z0 = sZ + gb * 72;
            const float* z1 = sZ + (gb + 64) * 72;
            const float* xr = sX + gb * 36;
            float zi = z0[ghd]      + z0[32 + ghd] + z1[ghd]      + z1[32 + ghd] + xr[ghd];
            float zf = z0[8 + ghd]  + z0[40 + ghd] + z1[8 + ghd]  + z1[40 + ghd] + xr[8 + ghd];
            float zg = z0[16 + ghd] + z0[48 + ghd] + z1[16 + ghd] + z1[48 + ghd] + xr[16 + ghd];
            float zo = z0[24 + ghd] + z0[56 + ghd] + z1[24 + ghd] + z1[56 + ghd] + xr[24 + ghd];
            float cn = sigm_(zf) * creg + sigm_(zi) * tanhf_(zg);
            float hn = sigm_(zo) * tanhf_(cn);
            creg = cn;

            __nv_bfloat16 hi = __float2bfloat16(hn);
            __nv_bfloat16 lo = __float2bfloat16(hn - __bfloat162float(hi));
            const int nb = (t + 1) & 1;
            const int off = gb * CH + hj + ghd;
            g_hbf[nb][0][off] = __bfloat16_as_ushort(hi);
            g_hbf[nb][1][off] = __bfloat16_as_ushort(lo);

            if (ybh) {   // layer 1: publish y as bf16 hi/lo (A operand of proj2)
                const size_t moff = (size_t)(t * 64 + gb) * CH + hj + ghd;
                ybh[moff] = __bfloat16_as_ushort(hi);
                ybl[moff] = __bfloat16_as_ushort(lo);
            } else {     // layer 2: float output
                y[(size_t)t * y_ts + (size_t)gb * y_bs + hj + ghd] = hn;
            }
            if (t == CT - 1) {
                hOut[off] = hn;
                cOut[off] = cn;
            }
        }
    }
}

// ============================================================================
extern "C" void kernel_launch(void* const* d_in, const int* in_sizes, int n_in,
                              void* d_out, int out_size)
{
    const int*   x   = (const int*)  d_in[0];
    const float* h01 = (const float*)d_in[1];
    const float* c01 = (const float*)d_in[2];
    const float* h02 = (const float*)d_in[3];
    const float* c02 = (const float*)d_in[4];
    const float* emb = (const float*)d_in[5];
    const float* W1  = (const float*)d_in[6];
    const float* U1  = (const float*)d_in[7];
    const float* b1  = (const float*)d_in[8];
    const float* W2  = (const float*)d_in[9];
    const float* U2  = (const float*)d_in[10];
    const float* b2  = (const float*)d_in[11];

    float* out = (float*)d_out;
    float* h1o = out + (size_t)CB * CT * CH;
    float* c1o = h1o + CB * CH;
    float* h2o = c1o + CB * CH;
    float* c2o = h2o + CB * CH;

    float* xzp;
    unsigned short *abh, *abl;
    cudaGetSymbolAddress((void**)&xzp, g_xz);
    cudaGetSymbolAddress((void**)&abh, g_abf);   // g_abf[0]
    abl = abh + (size_t)CT * CB * CH;            // g_abf[1]

    static int smem_set = 0;
    if (!smem_set) {
        cudaFuncSetAttribute(lstm_kernel,
                             cudaFuncAttributeMaxDynamicSharedMemorySize, SMW_BYTES);
        cudaFuncSetAttribute(mma_gemm_kernel,
                             cudaFuncAttributeMaxDynamicSharedMemorySize, GSM_BYTES);
        smem_set = 1;
    }

    dim3 gg(CG / 128, (CT * CB) / 128);   // (32, 64)

    // ---- layer 1 ----
    conv_w_kernel<<<(CE * CG + 255) / 256, 256>>>(W1, CE * CG);
    conv_emb_kernel<<<CT * CB, CE>>>(emb, x);
    mma_gemm_kernel<<<gg, 256, GSM_BYTES>>>(b1, xzp, CE);
    lstm_kernel<<<NCTA, LTHR, SMW_BYTES>>>(xzp, U1, nullptr, 0, 0,
                                           abh, abl, h01, c01, h1o, c1o);
    // ---- layer 2 ----
    conv_w_kernel<<<(CH * CG + 255) / 256, 256>>>(W2, CH * CG);
    mma_gemm_kernel<<<gg, 256, GSM_BYTES>>>(b2, xzp, CH);
    lstm_kernel<<<NCTA, LTHR, SMW_BYTES>>>(xzp, U2, out, CH, CT * CH,
                                           nullptr, nullptr, h02, c02, h2o, c2o);
}